// round 1
// baseline (speedup 1.0000x reference)
#include <cuda_runtime.h>
#include <cuda_bf16.h>
#include <math.h>

typedef __nv_bfloat16 bf16;

#define BATCH_ 2
#define SEQ_ 4096
#define HID_ 2560
#define HEADS_ 10
#define BW_ 256
#define MTOK_ (BATCH_*SEQ_)

static constexpr long MD = (long)MTOK_ * HID_;   // 20,971,520
static constexpr long DD = (long)HID_ * HID_;    //  6,553,600
static constexpr long GD = (long)BW_  * HID_;    //    655,360

// ---- scratch layout (single __device__ arena; no allocations anywhere) ----
static constexpr long O_XHI = 0;
static constexpr long O_XLO = O_XHI + MD*2;
static constexpr long O_CHI = O_XLO + MD*2;
static constexpr long O_CLO = O_CHI + MD*2;
static constexpr long O_HHI = O_CLO + MD*2;
static constexpr long O_HLO = O_HHI + MD*2;
static constexpr long O_WYH = O_HLO + MD*2;
static constexpr long O_WYL = O_WYH + DD*2;
static constexpr long O_WXH = O_WYL + DD*2;
static constexpr long O_WXL = O_WXH + DD*2;
static constexpr long O_WOH = O_WXL + DD*2;
static constexpr long O_WOL = O_WOH + DD*2;
static constexpr long O_IGH = O_WOL + DD*2;
static constexpr long O_IGL = O_IGH + GD*2;
static constexpr long O_AGH = O_IGL + GD*2;
static constexpr long O_AGL = O_AGH + GD*2;
static constexpr long O_YBR = O_AGL + GD*2;
static constexpr long O_XBR = O_YBR + MD*4;
static constexpr long O_CNV = O_XBR + MD*4;
static constexpr long O_GX  = O_CNV + MD*4;
static constexpr long O_GA  = O_GX  + MD*4;
static constexpr long O_A   = O_GA  + MD*4;
static constexpr long O_XN  = O_A   + MD*4;
static constexpr long O_TOTAL = O_XN + MD*4;

__device__ __align__(256) unsigned char g_scratch[O_TOTAL];

// =====================================================================
// elementwise kernels
// =====================================================================
__global__ void k_split(const float* __restrict__ src, bf16* __restrict__ hi,
                        bf16* __restrict__ lo, long n) {
    long i = (long)blockIdx.x * blockDim.x + threadIdx.x;
    if (i >= n) return;
    float v = src[i];
    bf16 h = __float2bfloat16(v);
    hi[i] = h;
    lo[i] = __float2bfloat16(v - __bfloat162float(h));
}

__global__ void k_conv(const float* __restrict__ xb, const float* __restrict__ cw,
                       const float* __restrict__ cb, float* __restrict__ cf,
                       bf16* __restrict__ chi, bf16* __restrict__ clo) {
    long i = (long)blockIdx.x * blockDim.x + threadIdx.x;
    if (i >= MD) return;
    int d = (int)(i % HID_);
    long bs = i / HID_;
    int s = (int)(bs % SEQ_);
    float acc = cb[d];
#pragma unroll
    for (int k = 0; k < 4; k++) {
        int ts = s + k - 3;
        if (ts >= 0) acc += xb[i + (long)(k - 3) * HID_] * cw[d * 4 + k];
    }
    cf[i] = acc;
    bf16 h = __float2bfloat16(acc);
    chi[i] = h;
    clo[i] = __float2bfloat16(acc - __bfloat162float(h));
}

__global__ void k_prep(const int* __restrict__ pos32, const float* __restrict__ ap,
                       const float* __restrict__ ga, const float* __restrict__ gx,
                       const float* __restrict__ cf, float* __restrict__ A,
                       float* __restrict__ XN) {
    long i = (long)blockIdx.x * blockDim.x + threadIdx.x;
    if (i >= MD) return;
    // dtype probe: position_ids = broadcast(arange). If stored as int64,
    // 32-bit word[1] (high half of element 0) is 0; if int32, word[1]=1.
    bool is64 = (pos32[1] == 0);
    int d = (int)(i % HID_);
    long bs = i / HID_;
    bool reset;
    if (is64) reset = (pos32[2 * bs] == 0) && (pos32[2 * bs + 1] == 0);
    else      reset = (pos32[bs] == 0);
    float apv = ap[d];
    float sp = (apv > 20.f) ? apv : log1pf(expf(apv));
    float la = -8.f * ga[i] * sp;
    float a = expf(la);
    float mult = reset ? 1.f : sqrtf(fmaxf(1.f - expf(2.f * la), 0.f));
    XN[i] = cf[i] * gx[i] * mult;
    A[i] = reset ? 0.f : a;
}

__global__ void k_scan(const float* __restrict__ A, const float* __restrict__ XN,
                       const float* __restrict__ Y, const float* __restrict__ ph,
                       bf16* __restrict__ hhi, bf16* __restrict__ hlo) {
    int d = blockIdx.x * blockDim.x + threadIdx.x;   // 0..HID_-1
    int b = blockIdx.y;
    float h = ph[(long)b * HID_ + d];
    long base = (long)b * SEQ_ * HID_ + d;
    for (int t = 0; t < SEQ_; t += 8) {
        float av[8], xv[8], yv[8];
#pragma unroll
        for (int j = 0; j < 8; j++) {
            long id = base + (long)(t + j) * HID_;
            av[j] = A[id]; xv[j] = XN[id]; yv[j] = Y[id];
        }
#pragma unroll
        for (int j = 0; j < 8; j++) {
            h = fmaf(av[j], h, xv[j]);
            float v = h * yv[j];
            bf16 hb = __float2bfloat16(v);
            long id = base + (long)(t + j) * HID_;
            hhi[id] = hb;
            hlo[id] = __float2bfloat16(v - __bfloat162float(hb));
        }
    }
}

// =====================================================================
// split-bf16 GEMM:  C[m,n] = sum_k A[m,k]*W[n,k] + bias[n]  (3-term Ootomo)
// tiles: 128x128x32, 8 warps (4x2), warp tile 32x64, mma.m16n8k16 bf16
// smem rows padded to 40 halves (80 B) -> 16B-aligned + bank-conflict-free
// =====================================================================
#define GBM 128
#define GBN 128
#define GBK 32
#define KP  40

__device__ __forceinline__ float gelu_tanh(float x) {
    float x3 = x * x * x;
    float t = tanhf(0.7978845608028654f * (x + 0.044715f * x3));
    return 0.5f * x * (1.f + t);
}

#define LDM4(r0, r1, r2, r3, addr)                                          \
    asm volatile("ldmatrix.sync.aligned.m8n8.x4.shared.b16 {%0,%1,%2,%3}, [%4];\n" \
                 : "=r"(r0), "=r"(r1), "=r"(r2), "=r"(r3) : "r"(addr))

#define MMA(d, a, b)                                                        \
    asm volatile("mma.sync.aligned.m16n8k16.row.col.f32.bf16.bf16.f32 "     \
                 "{%0,%1,%2,%3},{%4,%5,%6,%7},{%8,%9},{%0,%1,%2,%3};\n"     \
                 : "+f"(d[0]), "+f"(d[1]), "+f"(d[2]), "+f"(d[3])           \
                 : "r"(a[0]), "r"(a[1]), "r"(a[2]), "r"(a[3]),              \
                   "r"(b[0]), "r"(b[1]))

#define CP16(saddr, gptr)                                                   \
    asm volatile("cp.async.cg.shared.global [%0], [%1], 16;\n" ::           \
                 "r"(saddr), "l"(gptr))

template <int EPI>  // 0=bias, 1=bias+gelu, 2=bias+sigmoid
__global__ __launch_bounds__(256) void k_gemm(
    const bf16* __restrict__ Ahi, const bf16* __restrict__ Alo, int lda, long az,
    const bf16* __restrict__ Bhi, const bf16* __restrict__ Blo, int ldb, long bz,
    const float* __restrict__ bias, float* __restrict__ C, int ldc, long cz, int K) {
    extern __shared__ unsigned char smraw[];
    bf16* sA = (bf16*)smraw;                   // [2 stage][2 part][GBM][KP]
    bf16* sB = sA + 2 * 2 * GBM * KP;          // same shape

    const int tid = threadIdx.x;
    const int lane = tid & 31;
    const int warp = tid >> 5;
    const int wm = warp & 3, wn = warp >> 2;
    const int g = lane >> 2, tg = lane & 3;
    const long mbase = (long)blockIdx.y * GBM;
    const long nbase = (long)blockIdx.x * GBN;
    const long z = blockIdx.z;

    const bf16* pAh = Ahi + z * az + mbase * lda;
    const bf16* pAl = Alo + z * az + mbase * lda;
    const bf16* pBh = Bhi + z * bz + nbase * ldb;
    const bf16* pBl = Blo + z * bz + nbase * ldb;

    unsigned su  = (unsigned)__cvta_generic_to_shared(sA);
    unsigned sbu = (unsigned)__cvta_generic_to_shared(sB);

    float acc[2][8][4];
#pragma unroll
    for (int a = 0; a < 2; a++)
#pragma unroll
        for (int b = 0; b < 8; b++)
#pragma unroll
            for (int c = 0; c < 4; c++) acc[a][b][c] = 0.f;

    const int T = K / GBK;
    const int lrow = tid >> 2;
    const int lcol = (tid & 3) * 8;

    auto issue = [&](int t) {
        int st = t & 1;
        long ko = (long)t * GBK;
#pragma unroll
        for (int i = 0; i < 2; i++) {
            int r = lrow + i * 64;
            unsigned oh = (unsigned)((((st * 2 + 0) * GBM + r) * KP + lcol) * 2);
            unsigned ol = (unsigned)((((st * 2 + 1) * GBM + r) * KP + lcol) * 2);
            CP16(su + oh,  pAh + (long)r * lda + ko + lcol);
            CP16(su + ol,  pAl + (long)r * lda + ko + lcol);
            CP16(sbu + oh, pBh + (long)r * ldb + ko + lcol);
            CP16(sbu + ol, pBl + (long)r * ldb + ko + lcol);
        }
        asm volatile("cp.async.commit_group;\n" ::: "memory");
    };

    auto compute = [&](int st) {
#pragma unroll
        for (int kk = 0; kk < 2; kk++) {
            unsigned ah[2][4], al[2][4], bh[8][2], bl[8][2];
#pragma unroll
            for (int mt = 0; mt < 2; mt++) {
                int r = wm * 32 + mt * 16 + (lane & 7) + ((lane >> 3) & 1) * 8;
                int c = kk * 16 + (lane >> 4) * 8;
                unsigned a0 = su + (unsigned)((((st * 2 + 0) * GBM + r) * KP + c) * 2);
                LDM4(ah[mt][0], ah[mt][1], ah[mt][2], ah[mt][3], a0);
                unsigned a1 = su + (unsigned)((((st * 2 + 1) * GBM + r) * KP + c) * 2);
                LDM4(al[mt][0], al[mt][1], al[mt][2], al[mt][3], a1);
            }
#pragma unroll
            for (int np = 0; np < 4; np++) {
                int i = lane >> 3;
                int r = wn * 64 + np * 16 + ((i >> 1) & 1) * 8 + (lane & 7);
                int c = kk * 16 + (i & 1) * 8;
                unsigned b0 = sbu + (unsigned)((((st * 2 + 0) * GBM + r) * KP + c) * 2);
                LDM4(bh[2 * np][0], bh[2 * np][1], bh[2 * np + 1][0], bh[2 * np + 1][1], b0);
                unsigned b1 = sbu + (unsigned)((((st * 2 + 1) * GBM + r) * KP + c) * 2);
                LDM4(bl[2 * np][0], bl[2 * np][1], bl[2 * np + 1][0], bl[2 * np + 1][1], b1);
            }
#pragma unroll
            for (int mt = 0; mt < 2; mt++)
#pragma unroll
                for (int nt = 0; nt < 8; nt++) {
                    MMA(acc[mt][nt], ah[mt], bh[nt]);
                    MMA(acc[mt][nt], ah[mt], bl[nt]);
                    MMA(acc[mt][nt], al[mt], bh[nt]);
                }
        }
    };

    issue(0);
    for (int t = 0; t < T; t++) {
        if (t + 1 < T) {
            issue(t + 1);
            asm volatile("cp.async.wait_group 1;\n" ::: "memory");
        } else {
            asm volatile("cp.async.wait_group 0;\n" ::: "memory");
        }
        __syncthreads();
        compute(t & 1);
        __syncthreads();
    }

    // epilogue
#pragma unroll
    for (int mt = 0; mt < 2; mt++) {
        long r0 = mbase + wm * 32 + mt * 16 + g;
#pragma unroll
        for (int nt = 0; nt < 8; nt++) {
            long col = (long)(wn * 64 + nt * 8 + tg * 2);  // col within N block
            long gcol = nbase + col;
            float b0 = bias[gcol], b1 = bias[gcol + 1];
            float v0 = acc[mt][nt][0] + b0;
            float v1 = acc[mt][nt][1] + b1;
            float v2 = acc[mt][nt][2] + b0;
            float v3 = acc[mt][nt][3] + b1;
            if (EPI == 1) {
                v0 = gelu_tanh(v0); v1 = gelu_tanh(v1);
                v2 = gelu_tanh(v2); v3 = gelu_tanh(v3);
            } else if (EPI == 2) {
                v0 = 1.f / (1.f + expf(-v0)); v1 = 1.f / (1.f + expf(-v1));
                v2 = 1.f / (1.f + expf(-v2)); v3 = 1.f / (1.f + expf(-v3));
            }
            float* cp = C + z * cz;
            *(float2*)(cp + r0 * ldc + gcol)       = make_float2(v0, v1);
            *(float2*)(cp + (r0 + 8) * ldc + gcol) = make_float2(v2, v3);
        }
    }
}

// =====================================================================
// launch
// =====================================================================
extern "C" void kernel_launch(void* const* d_in, const int* in_sizes, int n_in,
                              void* d_out, int out_size) {
    const float* X       = (const float*)d_in[0];
    const int*   pos32   = (const int*)d_in[1];   // int32 or int64 (probed on device)
    const float* prevh   = (const float*)d_in[2];
    const float* w_y     = (const float*)d_in[3];
    const float* b_y     = (const float*)d_in[4];
    const float* w_x     = (const float*)d_in[5];
    const float* b_x     = (const float*)d_in[6];
    const float* w_out   = (const float*)d_in[7];
    const float* b_out   = (const float*)d_in[8];
    const float* conv_w  = (const float*)d_in[9];
    const float* conv_b  = (const float*)d_in[10];
    const float* a_param = (const float*)d_in[11];
    const float* ig_w    = (const float*)d_in[12];
    const float* ig_b    = (const float*)d_in[13];
    const float* ag_w    = (const float*)d_in[14];
    const float* ag_b    = (const float*)d_in[15];
    float* out = (float*)d_out;

    unsigned char* base = nullptr;
    cudaGetSymbolAddress((void**)&base, g_scratch);

    bf16*  xhi  = (bf16*)(base + O_XHI);  bf16* xlo  = (bf16*)(base + O_XLO);
    bf16*  chi  = (bf16*)(base + O_CHI);  bf16* clo  = (bf16*)(base + O_CLO);
    bf16*  hhi  = (bf16*)(base + O_HHI);  bf16* hlo  = (bf16*)(base + O_HLO);
    bf16*  wyh  = (bf16*)(base + O_WYH);  bf16* wyl  = (bf16*)(base + O_WYL);
    bf16*  wxh  = (bf16*)(base + O_WXH);  bf16* wxl  = (bf16*)(base + O_WXL);
    bf16*  woh  = (bf16*)(base + O_WOH);  bf16* wol  = (bf16*)(base + O_WOL);
    bf16*  igh  = (bf16*)(base + O_IGH);  bf16* igl  = (bf16*)(base + O_IGL);
    bf16*  agh  = (bf16*)(base + O_AGH);  bf16* agl  = (bf16*)(base + O_AGL);
    float* ybr  = (float*)(base + O_YBR);
    float* xbr  = (float*)(base + O_XBR);
    float* cnv  = (float*)(base + O_CNV);
    float* gx   = (float*)(base + O_GX);
    float* ga   = (float*)(base + O_GA);
    float* aarr = (float*)(base + O_A);
    float* xn   = (float*)(base + O_XN);

    const int SMEM = 2 * 2 * GBM * KP * 2 * 2;  // 81920 B
    cudaFuncSetAttribute((void*)k_gemm<0>, cudaFuncAttributeMaxDynamicSharedMemorySize, SMEM);
    cudaFuncSetAttribute((void*)k_gemm<1>, cudaFuncAttributeMaxDynamicSharedMemorySize, SMEM);
    cudaFuncSetAttribute((void*)k_gemm<2>, cudaFuncAttributeMaxDynamicSharedMemorySize, SMEM);

    const int TPB = 256;
    // 1) splits
    k_split<<<(int)((MD + TPB - 1) / TPB), TPB>>>(X, xhi, xlo, MD);
    k_split<<<(int)((DD + TPB - 1) / TPB), TPB>>>(w_y, wyh, wyl, DD);
    k_split<<<(int)((DD + TPB - 1) / TPB), TPB>>>(w_x, wxh, wxl, DD);
    k_split<<<(int)((DD + TPB - 1) / TPB), TPB>>>(w_out, woh, wol, DD);
    k_split<<<(int)((GD + TPB - 1) / TPB), TPB>>>(ig_w, igh, igl, GD);
    k_split<<<(int)((GD + TPB - 1) / TPB), TPB>>>(ag_w, agh, agl, GD);

    // 2) y-branch: gelu(X @ w_y^T + b_y)
    dim3 gBig(HID_ / GBN, MTOK_ / GBM, 1);
    k_gemm<1><<<gBig, TPB, SMEM>>>(xhi, xlo, HID_, 0, wyh, wyl, HID_, 0,
                                   b_y, ybr, HID_, 0, HID_);
    // 3) x-branch: X @ w_x^T + b_x
    k_gemm<0><<<gBig, TPB, SMEM>>>(xhi, xlo, HID_, 0, wxh, wxl, HID_, 0,
                                   b_x, xbr, HID_, 0, HID_);
    // 4) depthwise causal conv (+ bf16 split for the gate GEMMs)
    k_conv<<<(int)((MD + TPB - 1) / TPB), TPB>>>(xbr, conv_w, conv_b, cnv, chi, clo);

    // 5) block-diagonal gates (z = head)
    dim3 gGate(BW_ / GBN, MTOK_ / GBM, HEADS_);
    k_gemm<2><<<gGate, TPB, SMEM>>>(chi, clo, HID_, (long)BW_,
                                    igh, igl, BW_, (long)BW_ * BW_,
                                    ig_b, gx, HID_, (long)BW_, BW_);
    k_gemm<2><<<gGate, TPB, SMEM>>>(chi, clo, HID_, (long)BW_,
                                    agh, agl, BW_, (long)BW_ * BW_,
                                    ag_b, ga, HID_, (long)BW_, BW_);

    // 6) RG-LRU coefficient prep
    k_prep<<<(int)((MD + TPB - 1) / TPB), TPB>>>(pos32, a_param, ga, gx, cnv, aarr, xn);

    // 7) sequential scan, fused with *y_branch and bf16 split of the result
    k_scan<<<dim3(HID_ / TPB, BATCH_), TPB>>>(aarr, xn, ybr, prevh, hhi, hlo);

    // 8) out = (h*y) @ w_out^T + b_out
    k_gemm<0><<<gBig, TPB, SMEM>>>(hhi, hlo, HID_, 0, woh, wol, HID_, 0,
                                   b_out, out, HID_, 0, HID_);
}

// round 4
// speedup vs baseline: 1.1544x; 1.1544x over previous
#include <cuda_runtime.h>
#include <cuda_bf16.h>
#include <math.h>
#include <stdint.h>

typedef __nv_bfloat16 bf16;

#define BATCH_ 2
#define SEQ_ 4096
#define HID_ 2560
#define HEADS_ 10
#define BW_ 256
#define MTOK_ (BATCH_*SEQ_)
#define CH_ 128           // scan chunks
#define CL_ 32            // steps per chunk

static constexpr long MD = (long)MTOK_ * HID_;   // 20,971,520
static constexpr long DD = (long)HID_ * HID_;    //  6,553,600
static constexpr long GD = (long)BW_  * HID_;    //    655,360
static constexpr long CD = (long)BATCH_ * CH_ * HID_;  // 655,360

// ---- scratch arena ----
static constexpr long O_XHI = 0;
static constexpr long O_XLO = O_XHI + MD*2;
static constexpr long O_CHI = O_XLO + MD*2;
static constexpr long O_CLO = O_CHI + MD*2;
static constexpr long O_HHI = O_CLO + MD*2;
static constexpr long O_HLO = O_HHI + MD*2;
static constexpr long O_WYH = O_HLO + MD*2;
static constexpr long O_WYL = O_WYH + DD*2;
static constexpr long O_WXH = O_WYL + DD*2;
static constexpr long O_WXL = O_WXH + DD*2;
static constexpr long O_WOH = O_WXL + DD*2;
static constexpr long O_WOL = O_WOH + DD*2;
static constexpr long O_IGH = O_WOL + DD*2;
static constexpr long O_IGL = O_IGH + GD*2;
static constexpr long O_AGH = O_IGL + GD*2;
static constexpr long O_AGL = O_AGH + GD*2;
static constexpr long O_YBR = O_AGL + GD*2;
static constexpr long O_XBR = O_YBR + MD*4;
static constexpr long O_CNV = O_XBR + MD*4;
static constexpr long O_GX  = O_CNV + MD*4;
static constexpr long O_GA  = O_GX  + MD*4;
static constexpr long O_A   = O_GA  + MD*4;
static constexpr long O_XN  = O_A   + MD*4;
static constexpr long O_AC  = O_XN  + MD*4;
static constexpr long O_XC  = O_AC  + CD*4;
static constexpr long O_HC  = O_XC  + CD*4;
static constexpr long O_TOTAL = O_HC + CD*4;

__device__ __align__(256) unsigned char g_scratch[O_TOTAL];

// =====================================================================
// elementwise kernels (float4)
// =====================================================================
__device__ __forceinline__ void split1(float v, bf16& h, bf16& l) {
    h = __float2bfloat16(v);
    l = __float2bfloat16(v - __bfloat162float(h));
}

__global__ void k_split4(const float* __restrict__ src, bf16* __restrict__ hi,
                         bf16* __restrict__ lo, long n4) {
    long i = (long)blockIdx.x * blockDim.x + threadIdx.x;
    if (i >= n4) return;
    float4 v = ((const float4*)src)[i];
    bf16 h0, h1, h2, h3, l0, l1, l2, l3;
    split1(v.x, h0, l0); split1(v.y, h1, l1);
    split1(v.z, h2, l2); split1(v.w, h3, l3);
    ((__nv_bfloat162*)hi)[2 * i]     = __nv_bfloat162(h0, h1);
    ((__nv_bfloat162*)hi)[2 * i + 1] = __nv_bfloat162(h2, h3);
    ((__nv_bfloat162*)lo)[2 * i]     = __nv_bfloat162(l0, l1);
    ((__nv_bfloat162*)lo)[2 * i + 1] = __nv_bfloat162(l2, l3);
}

__global__ void k_conv4(const float* __restrict__ xb, const float* __restrict__ cw,
                        const float* __restrict__ cb, float* __restrict__ cf,
                        bf16* __restrict__ chi, bf16* __restrict__ clo) {
    long e = ((long)blockIdx.x * blockDim.x + threadIdx.x) * 4;
    if (e >= MD) return;
    int d = (int)(e % HID_);
    long bs = e / HID_;
    int s = (int)(bs % SEQ_);
    float4 acc = *(const float4*)(cb + d);
#pragma unroll
    for (int k = 0; k < 4; k++) {
        if (s + k - 3 >= 0) {
            float4 xv = *(const float4*)(xb + e + (long)(k - 3) * HID_);
            acc.x += xv.x * cw[(d + 0) * 4 + k];
            acc.y += xv.y * cw[(d + 1) * 4 + k];
            acc.z += xv.z * cw[(d + 2) * 4 + k];
            acc.w += xv.w * cw[(d + 3) * 4 + k];
        }
    }
    *(float4*)(cf + e) = acc;
    bf16 h0, h1, h2, h3, l0, l1, l2, l3;
    split1(acc.x, h0, l0); split1(acc.y, h1, l1);
    split1(acc.z, h2, l2); split1(acc.w, h3, l3);
    *(__nv_bfloat162*)(chi + e)     = __nv_bfloat162(h0, h1);
    *(__nv_bfloat162*)(chi + e + 2) = __nv_bfloat162(h2, h3);
    *(__nv_bfloat162*)(clo + e)     = __nv_bfloat162(l0, l1);
    *(__nv_bfloat162*)(clo + e + 2) = __nv_bfloat162(l2, l3);
}

__global__ void k_prep4(const int* __restrict__ pos32, const float* __restrict__ ap,
                        const float* __restrict__ ga, const float* __restrict__ gx,
                        const float* __restrict__ cf, float* __restrict__ A,
                        float* __restrict__ XN) {
    long e = ((long)blockIdx.x * blockDim.x + threadIdx.x) * 4;
    if (e >= MD) return;
    bool is64 = (pos32[1] == 0);
    int d = (int)(e % HID_);
    long bs = e / HID_;
    bool reset;
    if (is64) reset = (pos32[2 * bs] == 0) && (pos32[2 * bs + 1] == 0);
    else      reset = (pos32[bs] == 0);
    float4 apv = *(const float4*)(ap + d);
    float4 gav = *(const float4*)(ga + e);
    float4 gxv = *(const float4*)(gx + e);
    float4 cfv = *(const float4*)(cf + e);
    float4 Ao, Xo;
    float* apf = &apv.x; float* gaf = &gav.x; float* gxf = &gxv.x;
    float* cff = &cfv.x; float* Af = &Ao.x; float* Xf = &Xo.x;
#pragma unroll
    for (int j = 0; j < 4; j++) {
        float sp = (apf[j] > 20.f) ? apf[j] : log1pf(expf(apf[j]));
        float la = -8.f * gaf[j] * sp;
        float a = expf(la);
        float mult = reset ? 1.f : sqrtf(fmaxf(1.f - expf(2.f * la), 0.f));
        Xf[j] = cff[j] * gxf[j] * mult;
        Af[j] = reset ? 0.f : a;
    }
    *(float4*)(A + e) = Ao;
    *(float4*)(XN + e) = Xo;
}

// =====================================================================
// chunked scan (3 passes)
// =====================================================================
__global__ void k_scan1(const float* __restrict__ A, const float* __restrict__ XN,
                        float* __restrict__ Ac, float* __restrict__ Xc) {
    int d = blockIdx.x * blockDim.x + threadIdx.x;
    int c = blockIdx.y, b = blockIdx.z;
    long base = ((long)b * SEQ_ + (long)c * CL_) * HID_ + d;
    float h = 0.f, p = 1.f;
#pragma unroll 4
    for (int j = 0; j < CL_; j++) {
        long id = base + (long)j * HID_;
        float a = A[id];
        h = fmaf(a, h, XN[id]);
        p *= a;
    }
    long o = ((long)b * CH_ + c) * HID_ + d;
    Ac[o] = p; Xc[o] = h;
}

__global__ void k_scan2(const float* __restrict__ Ac, const float* __restrict__ Xc,
                        const float* __restrict__ ph, float* __restrict__ Hc) {
    int d = blockIdx.x * blockDim.x + threadIdx.x;
    int b = blockIdx.y;
    float h = ph[(long)b * HID_ + d];
    long base = (long)b * CH_ * HID_ + d;
    for (int c = 0; c < CH_; c += 8) {
        float av[8], xv[8];
#pragma unroll
        for (int j = 0; j < 8; j++) {
            long id = base + (long)(c + j) * HID_;
            av[j] = Ac[id]; xv[j] = Xc[id];
        }
#pragma unroll
        for (int j = 0; j < 8; j++) {
            long id = base + (long)(c + j) * HID_;
            Hc[id] = h;
            h = fmaf(av[j], h, xv[j]);
        }
    }
}

__global__ void k_scan3(const float* __restrict__ A, const float* __restrict__ XN,
                        const float* __restrict__ Y, const float* __restrict__ Hc,
                        bf16* __restrict__ hhi, bf16* __restrict__ hlo) {
    int d = blockIdx.x * blockDim.x + threadIdx.x;
    int c = blockIdx.y, b = blockIdx.z;
    long base = ((long)b * SEQ_ + (long)c * CL_) * HID_ + d;
    float h = Hc[((long)b * CH_ + c) * HID_ + d];
#pragma unroll 4
    for (int j = 0; j < CL_; j++) {
        long id = base + (long)j * HID_;
        h = fmaf(A[id], h, XN[id]);
        float v = h * Y[id];
        bf16 hb, lb;
        split1(v, hb, lb);
        hhi[id] = hb; hlo[id] = lb;
    }
}

// =====================================================================
// split-bf16 GEMM:  C[m,n] = sum_k A[m,k]*W[n,k] + bias[n]  (3-term Ootomo)
// tiles: 128x128x32, 8 warps (4x2), warp tile 32x64, mma.m16n8k16 bf16
// 3-stage cp.async pipeline, ONE __syncthreads per K-iter.
// smem rows padded to 40 halves (80 B) -> 16B-aligned + conflict-free LDSM
// =====================================================================
#define GBM 128
#define GBN 128
#define GBK 32
#define KP  40
#define NST 3
// halves per (stage,part) plane and per stage
#define PLN (GBM * KP)          // 5120 halves
#define STH (2 * PLN)           // 10240 halves per stage

__device__ __forceinline__ float gelu_tanh(float x) {
    float x3 = x * x * x;
    float t = tanhf(0.7978845608028654f * (x + 0.044715f * x3));
    return 0.5f * x * (1.f + t);
}

#define LDM4(r0, r1, r2, r3, addr)                                          \
    asm volatile("ldmatrix.sync.aligned.m8n8.x4.shared.b16 {%0,%1,%2,%3}, [%4];\n" \
                 : "=r"(r0), "=r"(r1), "=r"(r2), "=r"(r3) : "r"(addr))

#define MMA(d, a, b)                                                        \
    asm volatile("mma.sync.aligned.m16n8k16.row.col.f32.bf16.bf16.f32 "     \
                 "{%0,%1,%2,%3},{%4,%5,%6,%7},{%8,%9},{%0,%1,%2,%3};\n"     \
                 : "+f"(d[0]), "+f"(d[1]), "+f"(d[2]), "+f"(d[3])           \
                 : "r"(a[0]), "r"(a[1]), "r"(a[2]), "r"(a[3]),              \
                   "r"(b[0]), "r"(b[1]))

#define CP16(saddr, gptr)                                                   \
    asm volatile("cp.async.cg.shared.global [%0], [%1], 16;\n" ::           \
                 "r"(saddr), "l"(gptr))

template <int EPI>  // 0=bias, 1=bias+gelu, 2=bias+sigmoid
__global__ __launch_bounds__(256) void k_gemm(
    const bf16* __restrict__ Ahi, const bf16* __restrict__ Alo, int lda, long az,
    const bf16* __restrict__ Bhi, const bf16* __restrict__ Blo, int ldb, long bz,
    const float* __restrict__ bias, float* __restrict__ C, int ldc, long cz, int K) {
    extern __shared__ unsigned char smraw[];
    bf16* sA = (bf16*)smraw;                   // [NST][2 part][GBM][KP]
    bf16* sB = sA + NST * STH;

    const int tid = threadIdx.x;
    const int lane = tid & 31;
    const int warp = tid >> 5;
    const int wm = warp & 3, wn = warp >> 2;
    const int g = lane >> 2, tg = lane & 3;
    const long mbase = (long)blockIdx.y * GBM;
    const long nbase = (long)blockIdx.x * GBN;
    const long z = blockIdx.z;

    const bf16* pAh = Ahi + z * az + mbase * lda;
    const bf16* pAl = Alo + z * az + mbase * lda;
    const bf16* pBh = Bhi + z * bz + nbase * ldb;
    const bf16* pBl = Blo + z * bz + nbase * ldb;

    unsigned su  = (unsigned)__cvta_generic_to_shared(sA);
    unsigned sbu = (unsigned)__cvta_generic_to_shared(sB);

    float acc[2][8][4];
#pragma unroll
    for (int a = 0; a < 2; a++)
#pragma unroll
        for (int b = 0; b < 8; b++)
#pragma unroll
            for (int c = 0; c < 4; c++) acc[a][b][c] = 0.f;

    const int T = K / GBK;
    const int lrow = tid >> 2;
    const int lcol = (tid & 3) * 8;

    auto issue = [&](int t) {
        int st = t % NST;
        long ko = (long)t * GBK;
#pragma unroll
        for (int i = 0; i < 2; i++) {
            int r = lrow + i * 64;
            unsigned oh = (unsigned)((st * STH + 0 * PLN + r * KP + lcol) * 2);
            unsigned ol = (unsigned)((st * STH + 1 * PLN + r * KP + lcol) * 2);
            CP16(su + oh,  pAh + (long)r * lda + ko + lcol);
            CP16(su + ol,  pAl + (long)r * lda + ko + lcol);
            CP16(sbu + oh, pBh + (long)r * ldb + ko + lcol);
            CP16(sbu + ol, pBl + (long)r * ldb + ko + lcol);
        }
        asm volatile("cp.async.commit_group;\n" ::: "memory");
    };

    auto compute = [&](int st) {
#pragma unroll
        for (int kk = 0; kk < 2; kk++) {
            unsigned ah[2][4], al[2][4], bh[8][2], bl[8][2];
#pragma unroll
            for (int mt = 0; mt < 2; mt++) {
                int r = wm * 32 + mt * 16 + (lane & 7) + ((lane >> 3) & 1) * 8;
                int c = kk * 16 + (lane >> 4) * 8;
                unsigned a0 = su + (unsigned)((st * STH + 0 * PLN + r * KP + c) * 2);
                LDM4(ah[mt][0], ah[mt][1], ah[mt][2], ah[mt][3], a0);
                unsigned a1 = su + (unsigned)((st * STH + 1 * PLN + r * KP + c) * 2);
                LDM4(al[mt][0], al[mt][1], al[mt][2], al[mt][3], a1);
            }
#pragma unroll
            for (int np = 0; np < 4; np++) {
                int i = lane >> 3;
                int r = wn * 64 + np * 16 + ((i >> 1) & 1) * 8 + (lane & 7);
                int c = kk * 16 + (i & 1) * 8;
                unsigned b0 = sbu + (unsigned)((st * STH + 0 * PLN + r * KP + c) * 2);
                LDM4(bh[2 * np][0], bh[2 * np][1], bh[2 * np + 1][0], bh[2 * np + 1][1], b0);
                unsigned b1 = sbu + (unsigned)((st * STH + 1 * PLN + r * KP + c) * 2);
                LDM4(bl[2 * np][0], bl[2 * np][1], bl[2 * np + 1][0], bl[2 * np + 1][1], b1);
            }
#pragma unroll
            for (int mt = 0; mt < 2; mt++)
#pragma unroll
                for (int nt = 0; nt < 8; nt++) {
                    MMA(acc[mt][nt], ah[mt], bh[nt]);
                    MMA(acc[mt][nt], ah[mt], bl[nt]);
                    MMA(acc[mt][nt], al[mt], bh[nt]);
                }
        }
    };

    // prologue: fill 2 of 3 stages
    issue(0);
    issue(1);
    for (int t = 0; t < T; t++) {
        asm volatile("cp.async.wait_group 1;\n" ::: "memory");  // stage t ready
        __syncthreads();
        if (t + 2 < T) issue(t + 2);   // writes slot (t+2)%3 == (t-1)%3, free
        compute(t % NST);
    }

    // epilogue
#pragma unroll
    for (int mt = 0; mt < 2; mt++) {
        long r0 = mbase + wm * 32 + mt * 16 + g;
#pragma unroll
        for (int nt = 0; nt < 8; nt++) {
            long col = (long)(wn * 64 + nt * 8 + tg * 2);
            long gcol = nbase + col;
            float b0 = bias[gcol], b1 = bias[gcol + 1];
            float v0 = acc[mt][nt][0] + b0;
            float v1 = acc[mt][nt][1] + b1;
            float v2 = acc[mt][nt][2] + b0;
            float v3 = acc[mt][nt][3] + b1;
            if (EPI == 1) {
                v0 = gelu_tanh(v0); v1 = gelu_tanh(v1);
                v2 = gelu_tanh(v2); v3 = gelu_tanh(v3);
            } else if (EPI == 2) {
                v0 = 1.f / (1.f + expf(-v0)); v1 = 1.f / (1.f + expf(-v1));
                v2 = 1.f / (1.f + expf(-v2)); v3 = 1.f / (1.f + expf(-v3));
            }
            float* cp = C + z * cz;
            *(float2*)(cp + r0 * ldc + gcol)       = make_float2(v0, v1);
            *(float2*)(cp + (r0 + 8) * ldc + gcol) = make_float2(v2, v3);
        }
    }
}

// =====================================================================
// launch
// =====================================================================
extern "C" void kernel_launch(void* const* d_in, const int* in_sizes, int n_in,
                              void* d_out, int out_size) {
    const float* X       = (const float*)d_in[0];
    const int*   pos32   = (const int*)d_in[1];
    const float* prevh   = (const float*)d_in[2];
    const float* w_y     = (const float*)d_in[3];
    const float* b_y     = (const float*)d_in[4];
    const float* w_x     = (const float*)d_in[5];
    const float* b_x     = (const float*)d_in[6];
    const float* w_out   = (const float*)d_in[7];
    const float* b_out   = (const float*)d_in[8];
    const float* conv_w  = (const float*)d_in[9];
    const float* conv_b  = (const float*)d_in[10];
    const float* a_param = (const float*)d_in[11];
    const float* ig_w    = (const float*)d_in[12];
    const float* ig_b    = (const float*)d_in[13];
    const float* ag_w    = (const float*)d_in[14];
    const float* ag_b    = (const float*)d_in[15];
    float* out = (float*)d_out;

    unsigned char* base = nullptr;
    cudaGetSymbolAddress((void**)&base, g_scratch);

    bf16*  xhi  = (bf16*)(base + O_XHI);  bf16* xlo  = (bf16*)(base + O_XLO);
    bf16*  chi  = (bf16*)(base + O_CHI);  bf16* clo  = (bf16*)(base + O_CLO);
    bf16*  hhi  = (bf16*)(base + O_HHI);  bf16* hlo  = (bf16*)(base + O_HLO);
    bf16*  wyh  = (bf16*)(base + O_WYH);  bf16* wyl  = (bf16*)(base + O_WYL);
    bf16*  wxh  = (bf16*)(base + O_WXH);  bf16* wxl  = (bf16*)(base + O_WXL);
    bf16*  woh  = (bf16*)(base + O_WOH);  bf16* wol  = (bf16*)(base + O_WOL);
    bf16*  igh  = (bf16*)(base + O_IGH);  bf16* igl  = (bf16*)(base + O_IGL);
    bf16*  agh  = (bf16*)(base + O_AGH);  bf16* agl  = (bf16*)(base + O_AGL);
    float* ybr  = (float*)(base + O_YBR);
    float* xbr  = (float*)(base + O_XBR);
    float* cnv  = (float*)(base + O_CNV);
    float* gx   = (float*)(base + O_GX);
    float* ga   = (float*)(base + O_GA);
    float* aarr = (float*)(base + O_A);
    float* xn   = (float*)(base + O_XN);
    float* Ac   = (float*)(base + O_AC);
    float* Xc   = (float*)(base + O_XC);
    float* Hc   = (float*)(base + O_HC);

    // (A+B) = 2 planes of NST*STH halves, 2 bytes each = 122,880 B  (R3 bug:
    // an extra *2 pushed this to 245,760 B > 227 KB cap -> launch failure)
    const int SMEM = 2 * NST * STH * 2;
    cudaFuncSetAttribute((void*)k_gemm<0>, cudaFuncAttributeMaxDynamicSharedMemorySize, SMEM);
    cudaFuncSetAttribute((void*)k_gemm<1>, cudaFuncAttributeMaxDynamicSharedMemorySize, SMEM);
    cudaFuncSetAttribute((void*)k_gemm<2>, cudaFuncAttributeMaxDynamicSharedMemorySize, SMEM);

    const int TPB = 256;
    dim3 gBig(HID_ / GBN, MTOK_ / GBM, 1);

    // launches 1-5: splits (float4). Launch 6 = big GEMM (ncu -s 5 captures it).
    k_split4<<<(int)((MD / 4 + TPB - 1) / TPB), TPB>>>(X, xhi, xlo, MD / 4);
    k_split4<<<(int)((DD / 4 + TPB - 1) / TPB), TPB>>>(w_y, wyh, wyl, DD / 4);
    k_split4<<<(int)((DD / 4 + TPB - 1) / TPB), TPB>>>(w_x, wxh, wxl, DD / 4);
    k_split4<<<(int)((DD / 4 + TPB - 1) / TPB), TPB>>>(w_out, woh, wol, DD / 4);
    k_split4<<<(int)((GD / 4 + TPB - 1) / TPB), TPB>>>(ig_w, igh, igl, GD / 4);

    // 6) y-branch: gelu(X @ w_y^T + b_y)
    k_gemm<1><<<gBig, TPB, SMEM>>>(xhi, xlo, HID_, 0, wyh, wyl, HID_, 0,
                                   b_y, ybr, HID_, 0, HID_);

    k_split4<<<(int)((GD / 4 + TPB - 1) / TPB), TPB>>>(ag_w, agh, agl, GD / 4);

    // x-branch: X @ w_x^T + b_x
    k_gemm<0><<<gBig, TPB, SMEM>>>(xhi, xlo, HID_, 0, wxh, wxl, HID_, 0,
                                   b_x, xbr, HID_, 0, HID_);

    // depthwise causal conv (+ bf16 split)
    k_conv4<<<(int)((MD / 4 + TPB - 1) / TPB), TPB>>>(xbr, conv_w, conv_b, cnv, chi, clo);

    // block-diagonal gates (z = head)
    dim3 gGate(BW_ / GBN, MTOK_ / GBM, HEADS_);
    k_gemm<2><<<gGate, TPB, SMEM>>>(chi, clo, HID_, (long)BW_,
                                    igh, igl, BW_, (long)BW_ * BW_,
                                    ig_b, gx, HID_, (long)BW_, BW_);
    k_gemm<2><<<gGate, TPB, SMEM>>>(chi, clo, HID_, (long)BW_,
                                    agh, agl, BW_, (long)BW_ * BW_,
                                    ag_b, ga, HID_, (long)BW_, BW_);

    // RG-LRU coefficient prep
    k_prep4<<<(int)((MD / 4 + TPB - 1) / TPB), TPB>>>(pos32, a_param, ga, gx, cnv, aarr, xn);

    // chunked scan (3 passes), fused y-mult + bf16 split in pass 3
    dim3 gS(HID_ / TPB, CH_, BATCH_);
    k_scan1<<<gS, TPB>>>(aarr, xn, Ac, Xc);
    k_scan2<<<dim3(HID_ / TPB, BATCH_), TPB>>>(Ac, Xc, prevh, Hc);
    k_scan3<<<gS, TPB>>>(aarr, xn, ybr, Hc, hhi, hlo);

    // out = (h*y) @ w_out^T + b_out
    k_gemm<0><<<gBig, TPB, SMEM>>>(hhi, hlo, HID_, 0, woh, wol, HID_, 0,
                                   b_out, out, HID_, 0, HID_);
}

// round 6
// speedup vs baseline: 1.8105x; 1.5684x over previous
#include <cuda_runtime.h>
#include <cuda_fp16.h>
#include <math.h>
#include <stdint.h>

#define BATCH_ 2
#define SEQ_ 4096
#define HID_ 2560
#define HEADS_ 10
#define BW_ 256
#define MTOK_ (BATCH_*SEQ_)
#define CH_ 128           // scan chunks
#define CL_ 32            // steps per chunk

static constexpr long MD = (long)MTOK_ * HID_;   // 20,971,520
static constexpr long DD = (long)HID_ * HID_;    //  6,553,600
static constexpr long GD = (long)BW_  * HID_;    //    655,360
static constexpr long CD = (long)BATCH_ * CH_ * HID_;  // 655,360

// ---- scratch arena ----
static constexpr long O_XHI = 0;
static constexpr long O_XLO = O_XHI + MD*2;
static constexpr long O_CHI = O_XLO + MD*2;
static constexpr long O_CLO = O_CHI + MD*2;
static constexpr long O_HHI = O_CLO + MD*2;
static constexpr long O_HLO = O_HHI + MD*2;
static constexpr long O_WYH = O_HLO + MD*2;
static constexpr long O_WXH = O_WYH + DD*2;
static constexpr long O_WOH = O_WXH + DD*2;
static constexpr long O_IGH = O_WOH + DD*2;
static constexpr long O_IGL = O_IGH + GD*2;
static constexpr long O_AGH = O_IGL + GD*2;
static constexpr long O_AGL = O_AGH + GD*2;
static constexpr long O_YBR = O_AGL + GD*2;
static constexpr long O_XBR = O_YBR + MD*4;
static constexpr long O_CNV = O_XBR + MD*4;
static constexpr long O_GX  = O_CNV + MD*4;
static constexpr long O_GA  = O_GX  + MD*4;
static constexpr long O_A   = O_GA  + MD*4;
static constexpr long O_XN  = O_A   + MD*4;
static constexpr long O_AC  = O_XN  + MD*4;
static constexpr long O_XC  = O_AC  + CD*4;
static constexpr long O_HC  = O_XC  + CD*4;
static constexpr long O_TOTAL = O_HC + CD*4;

__device__ __align__(256) unsigned char g_scratch[O_TOTAL];

// =====================================================================
// elementwise kernels (float4)
// =====================================================================
__device__ __forceinline__ void split1(float v, half& h, half& l) {
    h = __float2half(v);
    l = __float2half(v - __half2float(h));
}

// hi+lo split
__global__ void k_split4(const float* __restrict__ src, half* __restrict__ hi,
                         half* __restrict__ lo, long n4) {
    long i = (long)blockIdx.x * blockDim.x + threadIdx.x;
    if (i >= n4) return;
    float4 v = ((const float4*)src)[i];
    half h0, h1, h2, h3, l0, l1, l2, l3;
    split1(v.x, h0, l0); split1(v.y, h1, l1);
    split1(v.z, h2, l2); split1(v.w, h3, l3);
    ((half2*)hi)[2 * i]     = __halves2half2(h0, h1);
    ((half2*)hi)[2 * i + 1] = __halves2half2(h2, h3);
    ((half2*)lo)[2 * i]     = __halves2half2(l0, l1);
    ((half2*)lo)[2 * i + 1] = __halves2half2(l2, l3);
}

// hi-only (weights of the 2-term GEMMs)
__global__ void k_splith(const float* __restrict__ src, half* __restrict__ hi, long n4) {
    long i = (long)blockIdx.x * blockDim.x + threadIdx.x;
    if (i >= n4) return;
    float4 v = ((const float4*)src)[i];
    ((half2*)hi)[2 * i]     = __halves2half2(__float2half(v.x), __float2half(v.y));
    ((half2*)hi)[2 * i + 1] = __halves2half2(__float2half(v.z), __float2half(v.w));
}

__global__ void k_conv4(const float* __restrict__ xb, const float* __restrict__ cw,
                        const float* __restrict__ cb, float* __restrict__ cf,
                        half* __restrict__ chi, half* __restrict__ clo) {
    long e = ((long)blockIdx.x * blockDim.x + threadIdx.x) * 4;
    if (e >= MD) return;
    int d = (int)(e % HID_);
    long bs = e / HID_;
    int s = (int)(bs % SEQ_);
    float4 acc = *(const float4*)(cb + d);
#pragma unroll
    for (int k = 0; k < 4; k++) {
        if (s + k - 3 >= 0) {
            float4 xv = *(const float4*)(xb + e + (long)(k - 3) * HID_);
            acc.x += xv.x * cw[(d + 0) * 4 + k];
            acc.y += xv.y * cw[(d + 1) * 4 + k];
            acc.z += xv.z * cw[(d + 2) * 4 + k];
            acc.w += xv.w * cw[(d + 3) * 4 + k];
        }
    }
    *(float4*)(cf + e) = acc;
    half h0, h1, h2, h3, l0, l1, l2, l3;
    split1(acc.x, h0, l0); split1(acc.y, h1, l1);
    split1(acc.z, h2, l2); split1(acc.w, h3, l3);
    *(half2*)(chi + e)     = __halves2half2(h0, h1);
    *(half2*)(chi + e + 2) = __halves2half2(h2, h3);
    *(half2*)(clo + e)     = __halves2half2(l0, l1);
    *(half2*)(clo + e + 2) = __halves2half2(l2, l3);
}

__global__ void k_prep4(const int* __restrict__ pos32, const float* __restrict__ ap,
                        const float* __restrict__ ga, const float* __restrict__ gx,
                        const float* __restrict__ cf, float* __restrict__ A,
                        float* __restrict__ XN) {
    long e = ((long)blockIdx.x * blockDim.x + threadIdx.x) * 4;
    if (e >= MD) return;
    bool is64 = (pos32[1] == 0);
    int d = (int)(e % HID_);
    long bs = e / HID_;
    bool reset;
    if (is64) reset = (pos32[2 * bs] == 0) && (pos32[2 * bs + 1] == 0);
    else      reset = (pos32[bs] == 0);
    float4 apv = *(const float4*)(ap + d);
    float4 gav = *(const float4*)(ga + e);
    float4 gxv = *(const float4*)(gx + e);
    float4 cfv = *(const float4*)(cf + e);
    float4 Ao, Xo;
    float* apf = &apv.x; float* gaf = &gav.x; float* gxf = &gxv.x;
    float* cff = &cfv.x; float* Af = &Ao.x; float* Xf = &Xo.x;
#pragma unroll
    for (int j = 0; j < 4; j++) {
        float sp = (apf[j] > 20.f) ? apf[j] : log1pf(expf(apf[j]));
        float la = -8.f * gaf[j] * sp;
        float a = expf(la);
        float mult = reset ? 1.f : sqrtf(fmaxf(1.f - expf(2.f * la), 0.f));
        Xf[j] = cff[j] * gxf[j] * mult;
        Af[j] = reset ? 0.f : a;
    }
    *(float4*)(A + e) = Ao;
    *(float4*)(XN + e) = Xo;
}

// =====================================================================
// chunked scan (3 passes)
// =====================================================================
__global__ void k_scan1(const float* __restrict__ A, const float* __restrict__ XN,
                        float* __restrict__ Ac, float* __restrict__ Xc) {
    int d = blockIdx.x * blockDim.x + threadIdx.x;
    int c = blockIdx.y, b = blockIdx.z;
    long base = ((long)b * SEQ_ + (long)c * CL_) * HID_ + d;
    float h = 0.f, p = 1.f;
#pragma unroll 4
    for (int j = 0; j < CL_; j++) {
        long id = base + (long)j * HID_;
        float a = A[id];
        h = fmaf(a, h, XN[id]);
        p *= a;
    }
    long o = ((long)b * CH_ + c) * HID_ + d;
    Ac[o] = p; Xc[o] = h;
}

__global__ void k_scan2(const float* __restrict__ Ac, const float* __restrict__ Xc,
                        const float* __restrict__ ph, float* __restrict__ Hc) {
    int d = blockIdx.x * blockDim.x + threadIdx.x;
    int b = blockIdx.y;
    float h = ph[(long)b * HID_ + d];
    long base = (long)b * CH_ * HID_ + d;
    for (int c = 0; c < CH_; c += 8) {
        float av[8], xv[8];
#pragma unroll
        for (int j = 0; j < 8; j++) {
            long id = base + (long)(c + j) * HID_;
            av[j] = Ac[id]; xv[j] = Xc[id];
        }
#pragma unroll
        for (int j = 0; j < 8; j++) {
            long id = base + (long)(c + j) * HID_;
            Hc[id] = h;
            h = fmaf(av[j], h, xv[j]);
        }
    }
}

__global__ void k_scan3(const float* __restrict__ A, const float* __restrict__ XN,
                        const float* __restrict__ Y, const float* __restrict__ Hc,
                        half* __restrict__ hhi, half* __restrict__ hlo) {
    int d = blockIdx.x * blockDim.x + threadIdx.x;
    int c = blockIdx.y, b = blockIdx.z;
    long base = ((long)b * SEQ_ + (long)c * CL_) * HID_ + d;
    float h = Hc[((long)b * CH_ + c) * HID_ + d];
#pragma unroll 4
    for (int j = 0; j < CL_; j++) {
        long id = base + (long)j * HID_;
        h = fmaf(A[id], h, XN[id]);
        float v = h * Y[id];
        half hb, lb;
        split1(v, hb, lb);
        hhi[id] = hb; hlo[id] = lb;
    }
}

// =====================================================================
// fp16-split GEMM:  C[m,n] = sum_k A[m,k]*W[n,k] + bias[n]
// TERMS=2: AhiWhi + AloWhi  (weights hi-only; err ~7e-5)
// TERMS=3: + AhiWlo         (gate GEMMs; protects the exp channel)
// tiles: 128x128x32, 8 warps (4x2), warp tile 32x64, mma.m16n8k16 f16
// 3-stage cp.async pipeline, one __syncthreads per K-iter.
// TERMS=2 stage = 3 planes = 30720 B -> 3 stages = 92160 B -> 2 CTAs/SM
// =====================================================================
#define GBM 128
#define GBN 128
#define GBK 32
#define KP  40
#define NST 3
#define PLN (GBM * KP)          // 5120 halves per plane

__device__ __forceinline__ float gelu_tanh(float x) {
    float x3 = x * x * x;
    float t = tanhf(0.7978845608028654f * (x + 0.044715f * x3));
    return 0.5f * x * (1.f + t);
}

#define LDM4(r0, r1, r2, r3, addr)                                          \
    asm volatile("ldmatrix.sync.aligned.m8n8.x4.shared.b16 {%0,%1,%2,%3}, [%4];\n" \
                 : "=r"(r0), "=r"(r1), "=r"(r2), "=r"(r3) : "r"(addr))

#define MMA(d, a, b)                                                        \
    asm volatile("mma.sync.aligned.m16n8k16.row.col.f32.f16.f16.f32 "       \
                 "{%0,%1,%2,%3},{%4,%5,%6,%7},{%8,%9},{%0,%1,%2,%3};\n"     \
                 : "+f"(d[0]), "+f"(d[1]), "+f"(d[2]), "+f"(d[3])           \
                 : "r"(a[0]), "r"(a[1]), "r"(a[2]), "r"(a[3]),              \
                   "r"(b[0]), "r"(b[1]))

#define CP16(saddr, gptr)                                                   \
    asm volatile("cp.async.cg.shared.global [%0], [%1], 16;\n" ::           \
                 "r"(saddr), "l"(gptr))

template <int EPI, int TERMS>  // EPI: 0=bias, 1=+gelu, 2=+sigmoid
__global__ __launch_bounds__(256, 2) void k_gemm(
    const half* __restrict__ Ahi, const half* __restrict__ Alo, int lda, long az,
    const half* __restrict__ Bhi, const half* __restrict__ Blo, int ldb, long bz,
    const float* __restrict__ bias, float* __restrict__ C, int ldc, long cz, int K) {
    constexpr int PL = 2 + (TERMS - 1);          // planes per stage
    extern __shared__ unsigned char smraw[];

    const int tid = threadIdx.x;
    const int lane = tid & 31;
    const int warp = tid >> 5;
    const int wm = warp & 3, wn = warp >> 2;
    const int g = lane >> 2, tg = lane & 3;
    const long mbase = (long)blockIdx.y * GBM;
    const long nbase = (long)blockIdx.x * GBN;
    const long z = blockIdx.z;

    const half* pAh = Ahi + z * az + mbase * lda;
    const half* pAl = Alo + z * az + mbase * lda;
    const half* pBh = Bhi + z * bz + nbase * ldb;
    const half* pBl = Blo + z * bz + nbase * ldb;

    unsigned su = (unsigned)__cvta_generic_to_shared(smraw);

    float acc[2][8][4];
#pragma unroll
    for (int a = 0; a < 2; a++)
#pragma unroll
        for (int b = 0; b < 8; b++)
#pragma unroll
            for (int c = 0; c < 4; c++) acc[a][b][c] = 0.f;

    const int T = K / GBK;
    const int lrow = tid >> 2;
    const int lcol = (tid & 3) * 8;

    auto issue = [&](int t) {
        int st = t % NST;
        long ko = (long)t * GBK;
        unsigned sb = su + (unsigned)(st * PL * PLN * 2);
#pragma unroll
        for (int i = 0; i < 2; i++) {
            int r = lrow + i * 64;
            unsigned off = (unsigned)((r * KP + lcol) * 2);
            CP16(sb + off,               pAh + (long)r * lda + ko + lcol);
            CP16(sb + off + PLN * 2,     pAl + (long)r * lda + ko + lcol);
            CP16(sb + off + 2 * PLN * 2, pBh + (long)r * ldb + ko + lcol);
            if (TERMS == 3)
                CP16(sb + off + 3 * PLN * 2, pBl + (long)r * ldb + ko + lcol);
        }
        asm volatile("cp.async.commit_group;\n" ::: "memory");
    };

    auto compute = [&](int st) {
        unsigned sb = su + (unsigned)(st * PL * PLN * 2);
#pragma unroll
        for (int kk = 0; kk < 2; kk++) {
            unsigned ah[2][4], al[2][4], bh[8][2], bl[8][2];
#pragma unroll
            for (int mt = 0; mt < 2; mt++) {
                int r = wm * 32 + mt * 16 + (lane & 7) + ((lane >> 3) & 1) * 8;
                int c = kk * 16 + (lane >> 4) * 8;
                unsigned a0 = sb + (unsigned)((r * KP + c) * 2);
                LDM4(ah[mt][0], ah[mt][1], ah[mt][2], ah[mt][3], a0);
                LDM4(al[mt][0], al[mt][1], al[mt][2], al[mt][3], a0 + PLN * 2);
            }
#pragma unroll
            for (int np = 0; np < 4; np++) {
                int i = lane >> 3;
                int r = wn * 64 + np * 16 + ((i >> 1) & 1) * 8 + (lane & 7);
                int c = kk * 16 + (i & 1) * 8;
                unsigned b0 = sb + (unsigned)((r * KP + c) * 2) + 2 * PLN * 2;
                LDM4(bh[2 * np][0], bh[2 * np][1], bh[2 * np + 1][0], bh[2 * np + 1][1], b0);
                if (TERMS == 3)
                    LDM4(bl[2 * np][0], bl[2 * np][1], bl[2 * np + 1][0], bl[2 * np + 1][1],
                         b0 + PLN * 2);
            }
#pragma unroll
            for (int mt = 0; mt < 2; mt++)
#pragma unroll
                for (int nt = 0; nt < 8; nt++) {
                    MMA(acc[mt][nt], ah[mt], bh[nt]);
                    MMA(acc[mt][nt], al[mt], bh[nt]);
                    if (TERMS == 3) MMA(acc[mt][nt], ah[mt], bl[nt]);
                }
        }
    };

    // prologue: fill 2 of 3 stages
    issue(0);
    issue(1);
    for (int t = 0; t < T; t++) {
        asm volatile("cp.async.wait_group 1;\n" ::: "memory");  // stage t ready
        __syncthreads();
        if (t + 2 < T) issue(t + 2);
        compute(t % NST);
    }

    // epilogue
#pragma unroll
    for (int mt = 0; mt < 2; mt++) {
        long r0 = mbase + wm * 32 + mt * 16 + g;
#pragma unroll
        for (int nt = 0; nt < 8; nt++) {
            long col = (long)(wn * 64 + nt * 8 + tg * 2);
            long gcol = nbase + col;
            float b0 = bias[gcol], b1 = bias[gcol + 1];
            float v0 = acc[mt][nt][0] + b0;
            float v1 = acc[mt][nt][1] + b1;
            float v2 = acc[mt][nt][2] + b0;
            float v3 = acc[mt][nt][3] + b1;
            if (EPI == 1) {
                v0 = gelu_tanh(v0); v1 = gelu_tanh(v1);
                v2 = gelu_tanh(v2); v3 = gelu_tanh(v3);
            } else if (EPI == 2) {
                v0 = 1.f / (1.f + expf(-v0)); v1 = 1.f / (1.f + expf(-v1));
                v2 = 1.f / (1.f + expf(-v2)); v3 = 1.f / (1.f + expf(-v3));
            }
            float* cp = C + z * cz;
            *(float2*)(cp + r0 * ldc + gcol)       = make_float2(v0, v1);
            *(float2*)(cp + (r0 + 8) * ldc + gcol) = make_float2(v2, v3);
        }
    }
}

// =====================================================================
// launch
// =====================================================================
extern "C" void kernel_launch(void* const* d_in, const int* in_sizes, int n_in,
                              void* d_out, int out_size) {
    const float* X       = (const float*)d_in[0];
    const int*   pos32   = (const int*)d_in[1];
    const float* prevh   = (const float*)d_in[2];
    const float* w_y     = (const float*)d_in[3];
    const float* b_y     = (const float*)d_in[4];
    const float* w_x     = (const float*)d_in[5];
    const float* b_x     = (const float*)d_in[6];
    const float* w_out   = (const float*)d_in[7];
    const float* b_out   = (const float*)d_in[8];
    const float* conv_w  = (const float*)d_in[9];
    const float* conv_b  = (const float*)d_in[10];
    const float* a_param = (const float*)d_in[11];
    const float* ig_w    = (const float*)d_in[12];
    const float* ig_b    = (const float*)d_in[13];
    const float* ag_w    = (const float*)d_in[14];
    const float* ag_b    = (const float*)d_in[15];
    float* out = (float*)d_out;

    unsigned char* base = nullptr;
    cudaGetSymbolAddress((void**)&base, g_scratch);

    half*  xhi  = (half*)(base + O_XHI);  half* xlo  = (half*)(base + O_XLO);
    half*  chi  = (half*)(base + O_CHI);  half* clo  = (half*)(base + O_CLO);
    half*  hhi  = (half*)(base + O_HHI);  half* hlo  = (half*)(base + O_HLO);
    half*  wyh  = (half*)(base + O_WYH);
    half*  wxh  = (half*)(base + O_WXH);
    half*  woh  = (half*)(base + O_WOH);
    half*  igh  = (half*)(base + O_IGH);  half* igl  = (half*)(base + O_IGL);
    half*  agh  = (half*)(base + O_AGH);  half* agl  = (half*)(base + O_AGL);
    float* ybr  = (float*)(base + O_YBR);
    float* xbr  = (float*)(base + O_XBR);
    float* cnv  = (float*)(base + O_CNV);
    float* gx   = (float*)(base + O_GX);
    float* ga   = (float*)(base + O_GA);
    float* aarr = (float*)(base + O_A);
    float* xn   = (float*)(base + O_XN);
    float* Ac   = (float*)(base + O_AC);
    float* Xc   = (float*)(base + O_XC);
    float* Hc   = (float*)(base + O_HC);

    const int SM2 = NST * 3 * PLN * 2;   // 92160 B  (2-term: A hi/lo + B hi)
    const int SM3 = NST * 4 * PLN * 2;   // 122880 B (3-term: + B lo)
    cudaFuncSetAttribute((void*)k_gemm<0,2>, cudaFuncAttributeMaxDynamicSharedMemorySize, SM2);
    cudaFuncSetAttribute((void*)k_gemm<1,2>, cudaFuncAttributeMaxDynamicSharedMemorySize, SM2);
    cudaFuncSetAttribute((void*)k_gemm<2,3>, cudaFuncAttributeMaxDynamicSharedMemorySize, SM3);

    const int TPB = 256;
    dim3 gBig(HID_ / GBN, MTOK_ / GBM, 1);

    // splits
    k_split4<<<(int)((MD / 4 + TPB - 1) / TPB), TPB>>>(X, xhi, xlo, MD / 4);
    k_splith<<<(int)((DD / 4 + TPB - 1) / TPB), TPB>>>(w_y, wyh, DD / 4);
    k_splith<<<(int)((DD / 4 + TPB - 1) / TPB), TPB>>>(w_x, wxh, DD / 4);
    k_splith<<<(int)((DD / 4 + TPB - 1) / TPB), TPB>>>(w_out, woh, DD / 4);
    k_split4<<<(int)((GD / 4 + TPB - 1) / TPB), TPB>>>(ig_w, igh, igl, GD / 4);

    // y-branch: gelu(X @ w_y^T + b_y)   (2-term)
    k_gemm<1,2><<<gBig, TPB, SM2>>>(xhi, xlo, HID_, 0, wyh, wyh, HID_, 0,
                                    b_y, ybr, HID_, 0, HID_);

    k_split4<<<(int)((GD / 4 + TPB - 1) / TPB), TPB>>>(ag_w, agh, agl, GD / 4);

    // x-branch: X @ w_x^T + b_x   (2-term)
    k_gemm<0,2><<<gBig, TPB, SM2>>>(xhi, xlo, HID_, 0, wxh, wxh, HID_, 0,
                                    b_x, xbr, HID_, 0, HID_);

    // depthwise causal conv (+ fp16 split)
    k_conv4<<<(int)((MD / 4 + TPB - 1) / TPB), TPB>>>(xbr, conv_w, conv_b, cnv, chi, clo);

    // block-diagonal gates (z = head) — 3-term, protects the exp channel
    dim3 gGate(BW_ / GBN, MTOK_ / GBM, HEADS_);
    k_gemm<2,3><<<gGate, TPB, SM3>>>(chi, clo, HID_, (long)BW_,
                                     igh, igl, BW_, (long)BW_ * BW_,
                                     ig_b, gx, HID_, (long)BW_, BW_);
    k_gemm<2,3><<<gGate, TPB, SM3>>>(chi, clo, HID_, (long)BW_,
                                     agh, agl, BW_, (long)BW_ * BW_,
                                     ag_b, ga, HID_, (long)BW_, BW_);

    // RG-LRU coefficient prep
    k_prep4<<<(int)((MD / 4 + TPB - 1) / TPB), TPB>>>(pos32, a_param, ga, gx, cnv, aarr, xn);

    // chunked scan (3 passes), fused y-mult + fp16 split in pass 3
    dim3 gS(HID_ / TPB, CH_, BATCH_);
    k_scan1<<<gS, TPB>>>(aarr, xn, Ac, Xc);
    k_scan2<<<dim3(HID_ / TPB, BATCH_), TPB>>>(Ac, Xc, prevh, Hc);
    k_scan3<<<gS, TPB>>>(aarr, xn, ybr, Hc, hhi, hlo);

    // out = (h*y) @ w_out^T + b_out   (2-term)
    k_gemm<0,2><<<gBig, TPB, SM2>>>(hhi, hlo, HID_, 0, woh, woh, HID_, 0,
                                    b_out, out, HID_, 0, HID_);
}

// round 7
// speedup vs baseline: 2.2484x; 1.2419x over previous
#include <cuda_runtime.h>
#include <cuda_fp16.h>
#include <math.h>
#include <stdint.h>

#define BATCH_ 2
#define SEQ_ 4096
#define HID_ 2560
#define HEADS_ 10
#define BW_ 256
#define MTOK_ (BATCH_*SEQ_)
#define CH_ 128           // scan chunks
#define CL_ 32            // steps per chunk

static constexpr long MD = (long)MTOK_ * HID_;   // 20,971,520
static constexpr long DD = (long)HID_ * HID_;    //  6,553,600
static constexpr long GD = (long)BW_  * HID_;    //    655,360
static constexpr long CD = (long)BATCH_ * CH_ * HID_;  // 655,360

// ---- scratch arena ----
static constexpr long O_XHI = 0;
static constexpr long O_XLO = O_XHI + MD*2;
static constexpr long O_CHI = O_XLO + MD*2;
static constexpr long O_CLO = O_CHI + MD*2;
static constexpr long O_HHI = O_CLO + MD*2;
static constexpr long O_WYH = O_HHI + MD*2;
static constexpr long O_WXH = O_WYH + DD*2;
static constexpr long O_WOH = O_WXH + DD*2;
static constexpr long O_IGH = O_WOH + DD*2;
static constexpr long O_IGL = O_IGH + GD*2;
static constexpr long O_AGH = O_IGL + GD*2;
static constexpr long O_AGL = O_AGH + GD*2;
static constexpr long O_SP8 = O_AGL + GD*2;
static constexpr long O_YBR = O_SP8 + HID_*4;
static constexpr long O_XBR = O_YBR + MD*4;
static constexpr long O_CNV = O_XBR + MD*4;
static constexpr long O_GX  = O_CNV + MD*4;
static constexpr long O_GA  = O_GX  + MD*4;
static constexpr long O_A   = O_GA  + MD*4;
static constexpr long O_XN  = O_A   + MD*4;
static constexpr long O_AC  = O_XN  + MD*4;
static constexpr long O_XC  = O_AC  + CD*4;
static constexpr long O_HC  = O_XC  + CD*4;
static constexpr long O_TOTAL = O_HC + CD*4;

__device__ __align__(256) unsigned char g_scratch[O_TOTAL];

// =====================================================================
// elementwise kernels (float4)
// =====================================================================
__device__ __forceinline__ void split1(float v, half& h, half& l) {
    h = __float2half(v);
    l = __float2half(v - __half2float(h));
}

// hi+lo split
__global__ void k_split4(const float* __restrict__ src, half* __restrict__ hi,
                         half* __restrict__ lo, long n4) {
    long i = (long)blockIdx.x * blockDim.x + threadIdx.x;
    if (i >= n4) return;
    float4 v = ((const float4*)src)[i];
    half h0, h1, h2, h3, l0, l1, l2, l3;
    split1(v.x, h0, l0); split1(v.y, h1, l1);
    split1(v.z, h2, l2); split1(v.w, h3, l3);
    ((half2*)hi)[2 * i]     = __halves2half2(h0, h1);
    ((half2*)hi)[2 * i + 1] = __halves2half2(h2, h3);
    ((half2*)lo)[2 * i]     = __halves2half2(l0, l1);
    ((half2*)lo)[2 * i + 1] = __halves2half2(l2, l3);
}

// hi-only
__global__ void k_splith(const float* __restrict__ src, half* __restrict__ hi, long n4) {
    long i = (long)blockIdx.x * blockDim.x + threadIdx.x;
    if (i >= n4) return;
    float4 v = ((const float4*)src)[i];
    ((half2*)hi)[2 * i]     = __halves2half2(__float2half(v.x), __float2half(v.y));
    ((half2*)hi)[2 * i + 1] = __halves2half2(__float2half(v.z), __float2half(v.w));
}

// per-channel -8*softplus(a_param)  (2560 elements, accurate path)
__global__ void k_sp(const float* __restrict__ ap, float* __restrict__ sp8) {
    int d = blockIdx.x * blockDim.x + threadIdx.x;
    if (d >= HID_) return;
    float v = ap[d];
    float sp = (v > 20.f) ? v : log1pf(expf(v));
    sp8[d] = -8.f * sp;
}

__global__ void k_conv4(const float* __restrict__ xb, const float* __restrict__ cw,
                        const float* __restrict__ cb, float* __restrict__ cf,
                        half* __restrict__ chi, half* __restrict__ clo) {
    long e = ((long)blockIdx.x * blockDim.x + threadIdx.x) * 4;
    if (e >= MD) return;
    int d = (int)(e % HID_);
    long bs = e / HID_;
    int s = (int)(bs % SEQ_);
    float4 acc = *(const float4*)(cb + d);
#pragma unroll
    for (int k = 0; k < 4; k++) {
        if (s + k - 3 >= 0) {
            float4 xv = *(const float4*)(xb + e + (long)(k - 3) * HID_);
            acc.x += xv.x * cw[(d + 0) * 4 + k];
            acc.y += xv.y * cw[(d + 1) * 4 + k];
            acc.z += xv.z * cw[(d + 2) * 4 + k];
            acc.w += xv.w * cw[(d + 3) * 4 + k];
        }
    }
    *(float4*)(cf + e) = acc;
    half h0, h1, h2, h3, l0, l1, l2, l3;
    split1(acc.x, h0, l0); split1(acc.y, h1, l1);
    split1(acc.z, h2, l2); split1(acc.w, h3, l3);
    *(half2*)(chi + e)     = __halves2half2(h0, h1);
    *(half2*)(chi + e + 2) = __halves2half2(h2, h3);
    *(half2*)(clo + e)     = __halves2half2(l0, l1);
    *(half2*)(clo + e + 2) = __halves2half2(l2, l3);
}

__global__ void k_prep4(const int* __restrict__ pos32, const float* __restrict__ sp8,
                        const float* __restrict__ ga, const float* __restrict__ gx,
                        const float* __restrict__ cf, float* __restrict__ A,
                        float* __restrict__ XN) {
    long e = ((long)blockIdx.x * blockDim.x + threadIdx.x) * 4;
    if (e >= MD) return;
    bool is64 = (pos32[1] == 0);
    int d = (int)(e % HID_);
    long bs = e / HID_;
    bool reset;
    if (is64) reset = (pos32[2 * bs] == 0) && (pos32[2 * bs + 1] == 0);
    else      reset = (pos32[bs] == 0);
    float4 spv = *(const float4*)(sp8 + d);
    float4 gav = *(const float4*)(ga + e);
    float4 gxv = *(const float4*)(gx + e);
    float4 cfv = *(const float4*)(cf + e);
    float4 Ao, Xo;
    float* spf = &spv.x; float* gaf = &gav.x; float* gxf = &gxv.x;
    float* cff = &cfv.x; float* Af = &Ao.x; float* Xf = &Xo.x;
#pragma unroll
    for (int j = 0; j < 4; j++) {
        float la = gaf[j] * spf[j];          // -8 * gate_a * softplus(ap)
        float a = __expf(la);                // rel err ~2^-21, fine
        float a2 = a * a;                    // == exp(2*la)
        float mult = reset ? 1.f : sqrtf(fmaxf(1.f - a2, 0.f));
        Xf[j] = cff[j] * gxf[j] * mult;
        Af[j] = reset ? 0.f : a;
    }
    *(float4*)(A + e) = Ao;
    *(float4*)(XN + e) = Xo;
}

// =====================================================================
// chunked scan (3 passes)
// =====================================================================
__global__ void k_scan1(const float* __restrict__ A, const float* __restrict__ XN,
                        float* __restrict__ Ac, float* __restrict__ Xc) {
    int d = blockIdx.x * blockDim.x + threadIdx.x;
    int c = blockIdx.y, b = blockIdx.z;
    long base = ((long)b * SEQ_ + (long)c * CL_) * HID_ + d;
    float h = 0.f, p = 1.f;
#pragma unroll 4
    for (int j = 0; j < CL_; j++) {
        long id = base + (long)j * HID_;
        float a = A[id];
        h = fmaf(a, h, XN[id]);
        p *= a;
    }
    long o = ((long)b * CH_ + c) * HID_ + d;
    Ac[o] = p; Xc[o] = h;
}

__global__ void k_scan2(const float* __restrict__ Ac, const float* __restrict__ Xc,
                        const float* __restrict__ ph, float* __restrict__ Hc) {
    int d = blockIdx.x * blockDim.x + threadIdx.x;
    int b = blockIdx.y;
    float h = ph[(long)b * HID_ + d];
    long base = (long)b * CH_ * HID_ + d;
    for (int c = 0; c < CH_; c += 8) {
        float av[8], xv[8];
#pragma unroll
        for (int j = 0; j < 8; j++) {
            long id = base + (long)(c + j) * HID_;
            av[j] = Ac[id]; xv[j] = Xc[id];
        }
#pragma unroll
        for (int j = 0; j < 8; j++) {
            long id = base + (long)(c + j) * HID_;
            Hc[id] = h;
            h = fmaf(av[j], h, xv[j]);
        }
    }
}

__global__ void k_scan3(const float* __restrict__ A, const float* __restrict__ XN,
                        const float* __restrict__ Y, const float* __restrict__ Hc,
                        half* __restrict__ hhi) {
    int d = blockIdx.x * blockDim.x + threadIdx.x;
    int c = blockIdx.y, b = blockIdx.z;
    long base = ((long)b * SEQ_ + (long)c * CL_) * HID_ + d;
    float h = Hc[((long)b * CH_ + c) * HID_ + d];
#pragma unroll 4
    for (int j = 0; j < CL_; j++) {
        long id = base + (long)j * HID_;
        h = fmaf(A[id], h, XN[id]);
        hhi[id] = __float2half(h * Y[id]);   // out GEMM is 1-term; hi only
    }
}

// =====================================================================
// fp16-split GEMM:  C[m,n] = sum_k A[m,k]*W[n,k] + bias[n]
// TERMS=1: AhiWhi                  (y-branch, out GEMM)
// TERMS=2: + AloWhi                (x-branch — protects recurrence input)
// TERMS=3: + AhiWlo                (gate GEMMs — protects the exp channel)
// tiles: 128x128x32, 8 warps (4x2), warp tile 32x64, mma.m16n8k16 f16
// 3-stage cp.async pipeline, one __syncthreads per K-iter.
// =====================================================================
#define GBM 128
#define GBN 128
#define GBK 32
#define KP  40
#define NST 3
#define PLN (GBM * KP)          // 5120 halves per plane

// fast, saturation-safe tanh/sigmoid via __expf (rel err ~1e-6)
__device__ __forceinline__ float fast_tanh(float u) {
    float e = __expf(2.f * u);               // +inf for big u -> t=1; 0 for small -> t=-1
    return 1.f - 2.f / (e + 1.f);
}
__device__ __forceinline__ float gelu_tanh(float x) {
    float x3 = x * x * x;
    float t = fast_tanh(0.7978845608028654f * (x + 0.044715f * x3));
    return 0.5f * x * (1.f + t);
}
__device__ __forceinline__ float fast_sigmoid(float v) {
    return 1.f / (1.f + __expf(-v));
}

#define LDM4(r0, r1, r2, r3, addr)                                          \
    asm volatile("ldmatrix.sync.aligned.m8n8.x4.shared.b16 {%0,%1,%2,%3}, [%4];\n" \
                 : "=r"(r0), "=r"(r1), "=r"(r2), "=r"(r3) : "r"(addr))

#define MMA(d, a, b)                                                        \
    asm volatile("mma.sync.aligned.m16n8k16.row.col.f32.f16.f16.f32 "       \
                 "{%0,%1,%2,%3},{%4,%5,%6,%7},{%8,%9},{%0,%1,%2,%3};\n"     \
                 : "+f"(d[0]), "+f"(d[1]), "+f"(d[2]), "+f"(d[3])           \
                 : "r"(a[0]), "r"(a[1]), "r"(a[2]), "r"(a[3]),              \
                   "r"(b[0]), "r"(b[1]))

#define CP16(saddr, gptr)                                                   \
    asm volatile("cp.async.cg.shared.global [%0], [%1], 16;\n" ::           \
                 "r"(saddr), "l"(gptr))

template <int EPI, int TERMS>  // EPI: 0=bias, 1=+gelu, 2=+sigmoid
__global__ __launch_bounds__(256, 2) void k_gemm(
    const half* __restrict__ Ahi, const half* __restrict__ Alo, int lda, long az,
    const half* __restrict__ Bhi, const half* __restrict__ Blo, int ldb, long bz,
    const float* __restrict__ bias, float* __restrict__ C, int ldc, long cz, int K) {
    constexpr int PL = TERMS + 1;                 // planes per stage
    constexpr int PBH = (TERMS >= 2) ? 2 : 1;     // B-hi plane index
    extern __shared__ unsigned char smraw[];

    const int tid = threadIdx.x;
    const int lane = tid & 31;
    const int warp = tid >> 5;
    const int wm = warp & 3, wn = warp >> 2;
    const int g = lane >> 2, tg = lane & 3;
    const long mbase = (long)blockIdx.y * GBM;
    const long nbase = (long)blockIdx.x * GBN;
    const long z = blockIdx.z;

    const half* pAh = Ahi + z * az + mbase * lda;
    const half* pAl = Alo + z * az + mbase * lda;
    const half* pBh = Bhi + z * bz + nbase * ldb;
    const half* pBl = Blo + z * bz + nbase * ldb;

    unsigned su = (unsigned)__cvta_generic_to_shared(smraw);

    float acc[2][8][4];
#pragma unroll
    for (int a = 0; a < 2; a++)
#pragma unroll
        for (int b = 0; b < 8; b++)
#pragma unroll
            for (int c = 0; c < 4; c++) acc[a][b][c] = 0.f;

    const int T = K / GBK;
    const int lrow = tid >> 2;
    const int lcol = (tid & 3) * 8;

    auto issue = [&](int t) {
        int st = t % NST;
        long ko = (long)t * GBK;
        unsigned sb = su + (unsigned)(st * PL * PLN * 2);
#pragma unroll
        for (int i = 0; i < 2; i++) {
            int r = lrow + i * 64;
            unsigned off = (unsigned)((r * KP + lcol) * 2);
            CP16(sb + off, pAh + (long)r * lda + ko + lcol);
            if (TERMS >= 2)
                CP16(sb + off + PLN * 2, pAl + (long)r * lda + ko + lcol);
            CP16(sb + off + PBH * PLN * 2, pBh + (long)r * ldb + ko + lcol);
            if (TERMS == 3)
                CP16(sb + off + 3 * PLN * 2, pBl + (long)r * ldb + ko + lcol);
        }
        asm volatile("cp.async.commit_group;\n" ::: "memory");
    };

    auto compute = [&](int st) {
        unsigned sb = su + (unsigned)(st * PL * PLN * 2);
#pragma unroll
        for (int kk = 0; kk < 2; kk++) {
            unsigned ah[2][4], al[2][4], bh[8][2], bl[8][2];
#pragma unroll
            for (int mt = 0; mt < 2; mt++) {
                int r = wm * 32 + mt * 16 + (lane & 7) + ((lane >> 3) & 1) * 8;
                int c = kk * 16 + (lane >> 4) * 8;
                unsigned a0 = sb + (unsigned)((r * KP + c) * 2);
                LDM4(ah[mt][0], ah[mt][1], ah[mt][2], ah[mt][3], a0);
                if (TERMS >= 2)
                    LDM4(al[mt][0], al[mt][1], al[mt][2], al[mt][3], a0 + PLN * 2);
            }
#pragma unroll
            for (int np = 0; np < 4; np++) {
                int i = lane >> 3;
                int r = wn * 64 + np * 16 + ((i >> 1) & 1) * 8 + (lane & 7);
                int c = kk * 16 + (i & 1) * 8;
                unsigned b0 = sb + (unsigned)((r * KP + c) * 2) + PBH * PLN * 2;
                LDM4(bh[2 * np][0], bh[2 * np][1], bh[2 * np + 1][0], bh[2 * np + 1][1], b0);
                if (TERMS == 3)
                    LDM4(bl[2 * np][0], bl[2 * np][1], bl[2 * np + 1][0], bl[2 * np + 1][1],
                         b0 + PLN * 2);
            }
#pragma unroll
            for (int mt = 0; mt < 2; mt++)
#pragma unroll
                for (int nt = 0; nt < 8; nt++) {
                    MMA(acc[mt][nt], ah[mt], bh[nt]);
                    if (TERMS >= 2) MMA(acc[mt][nt], al[mt], bh[nt]);
                    if (TERMS == 3) MMA(acc[mt][nt], ah[mt], bl[nt]);
                }
        }
    };

    // prologue: fill 2 of 3 stages
    issue(0);
    issue(1);
    for (int t = 0; t < T; t++) {
        asm volatile("cp.async.wait_group 1;\n" ::: "memory");  // stage t ready
        __syncthreads();
        if (t + 2 < T) issue(t + 2);
        compute(t % NST);
    }

    // epilogue
#pragma unroll
    for (int mt = 0; mt < 2; mt++) {
        long r0 = mbase + wm * 32 + mt * 16 + g;
#pragma unroll
        for (int nt = 0; nt < 8; nt++) {
            long col = (long)(wn * 64 + nt * 8 + tg * 2);
            long gcol = nbase + col;
            float b0 = bias[gcol], b1 = bias[gcol + 1];
            float v0 = acc[mt][nt][0] + b0;
            float v1 = acc[mt][nt][1] + b1;
            float v2 = acc[mt][nt][2] + b0;
            float v3 = acc[mt][nt][3] + b1;
            if (EPI == 1) {
                v0 = gelu_tanh(v0); v1 = gelu_tanh(v1);
                v2 = gelu_tanh(v2); v3 = gelu_tanh(v3);
            } else if (EPI == 2) {
                v0 = fast_sigmoid(v0); v1 = fast_sigmoid(v1);
                v2 = fast_sigmoid(v2); v3 = fast_sigmoid(v3);
            }
            float* cp = C + z * cz;
            *(float2*)(cp + r0 * ldc + gcol)       = make_float2(v0, v1);
            *(float2*)(cp + (r0 + 8) * ldc + gcol) = make_float2(v2, v3);
        }
    }
}

// =====================================================================
// launch
// =====================================================================
extern "C" void kernel_launch(void* const* d_in, const int* in_sizes, int n_in,
                              void* d_out, int out_size) {
    const float* X       = (const float*)d_in[0];
    const int*   pos32   = (const int*)d_in[1];
    const float* prevh   = (const float*)d_in[2];
    const float* w_y     = (const float*)d_in[3];
    const float* b_y     = (const float*)d_in[4];
    const float* w_x     = (const float*)d_in[5];
    const float* b_x     = (const float*)d_in[6];
    const float* w_out   = (const float*)d_in[7];
    const float* b_out   = (const float*)d_in[8];
    const float* conv_w  = (const float*)d_in[9];
    const float* conv_b  = (const float*)d_in[10];
    const float* a_param = (const float*)d_in[11];
    const float* ig_w    = (const float*)d_in[12];
    const float* ig_b    = (const float*)d_in[13];
    const float* ag_w    = (const float*)d_in[14];
    const float* ag_b    = (const float*)d_in[15];
    float* out = (float*)d_out;

    unsigned char* base = nullptr;
    cudaGetSymbolAddress((void**)&base, g_scratch);

    half*  xhi  = (half*)(base + O_XHI);  half* xlo  = (half*)(base + O_XLO);
    half*  chi  = (half*)(base + O_CHI);  half* clo  = (half*)(base + O_CLO);
    half*  hhi  = (half*)(base + O_HHI);
    half*  wyh  = (half*)(base + O_WYH);
    half*  wxh  = (half*)(base + O_WXH);
    half*  woh  = (half*)(base + O_WOH);
    half*  igh  = (half*)(base + O_IGH);  half* igl  = (half*)(base + O_IGL);
    half*  agh  = (half*)(base + O_AGH);  half* agl  = (half*)(base + O_AGL);
    float* sp8  = (float*)(base + O_SP8);
    float* ybr  = (float*)(base + O_YBR);
    float* xbr  = (float*)(base + O_XBR);
    float* cnv  = (float*)(base + O_CNV);
    float* gx   = (float*)(base + O_GX);
    float* ga   = (float*)(base + O_GA);
    float* aarr = (float*)(base + O_A);
    float* xn   = (float*)(base + O_XN);
    float* Ac   = (float*)(base + O_AC);
    float* Xc   = (float*)(base + O_XC);
    float* Hc   = (float*)(base + O_HC);

    const int SM1 = NST * 2 * PLN * 2;   // 61440 B  (1-term: A hi + B hi)
    const int SM2 = NST * 3 * PLN * 2;   // 92160 B  (2-term: + A lo)
    const int SM3 = NST * 4 * PLN * 2;   // 122880 B (3-term: + B lo)
    cudaFuncSetAttribute((void*)k_gemm<1,1>, cudaFuncAttributeMaxDynamicSharedMemorySize, SM1);
    cudaFuncSetAttribute((void*)k_gemm<0,1>, cudaFuncAttributeMaxDynamicSharedMemorySize, SM1);
    cudaFuncSetAttribute((void*)k_gemm<0,2>, cudaFuncAttributeMaxDynamicSharedMemorySize, SM2);
    cudaFuncSetAttribute((void*)k_gemm<2,3>, cudaFuncAttributeMaxDynamicSharedMemorySize, SM3);

    const int TPB = 256;
    dim3 gBig(HID_ / GBN, MTOK_ / GBM, 1);

    // splits + per-channel softplus table
    k_split4<<<(int)((MD / 4 + TPB - 1) / TPB), TPB>>>(X, xhi, xlo, MD / 4);
    k_splith<<<(int)((DD / 4 + TPB - 1) / TPB), TPB>>>(w_y, wyh, DD / 4);
    k_splith<<<(int)((DD / 4 + TPB - 1) / TPB), TPB>>>(w_x, wxh, DD / 4);
    k_splith<<<(int)((DD / 4 + TPB - 1) / TPB), TPB>>>(w_out, woh, DD / 4);
    k_split4<<<(int)((GD / 4 + TPB - 1) / TPB), TPB>>>(ig_w, igh, igl, GD / 4);
    k_sp<<<(HID_ + TPB - 1) / TPB, TPB>>>(a_param, sp8);

    // y-branch: gelu(X @ w_y^T + b_y)   (1-term)
    k_gemm<1,1><<<gBig, TPB, SM1>>>(xhi, xhi, HID_, 0, wyh, wyh, HID_, 0,
                                    b_y, ybr, HID_, 0, HID_);

    k_split4<<<(int)((GD / 4 + TPB - 1) / TPB), TPB>>>(ag_w, agh, agl, GD / 4);

    // x-branch: X @ w_x^T + b_x   (2-term)
    k_gemm<0,2><<<gBig, TPB, SM2>>>(xhi, xlo, HID_, 0, wxh, wxh, HID_, 0,
                                    b_x, xbr, HID_, 0, HID_);

    // depthwise causal conv (+ fp16 split)
    k_conv4<<<(int)((MD / 4 + TPB - 1) / TPB), TPB>>>(xbr, conv_w, conv_b, cnv, chi, clo);

    // block-diagonal gates (z = head) — 3-term, protects the exp channel
    dim3 gGate(BW_ / GBN, MTOK_ / GBM, HEADS_);
    k_gemm<2,3><<<gGate, TPB, SM3>>>(chi, clo, HID_, (long)BW_,
                                     igh, igl, BW_, (long)BW_ * BW_,
                                     ig_b, gx, HID_, (long)BW_, BW_);
    k_gemm<2,3><<<gGate, TPB, SM3>>>(chi, clo, HID_, (long)BW_,
                                     agh, agl, BW_, (long)BW_ * BW_,
                                     ag_b, ga, HID_, (long)BW_, BW_);

    // RG-LRU coefficient prep (2 MUFU/element)
    k_prep4<<<(int)((MD / 4 + TPB - 1) / TPB), TPB>>>(pos32, sp8, ga, gx, cnv, aarr, xn);

    // chunked scan (3 passes), fused y-mult + fp16 convert in pass 3
    dim3 gS(HID_ / TPB, CH_, BATCH_);
    k_scan1<<<gS, TPB>>>(aarr, xn, Ac, Xc);
    k_scan2<<<dim3(HID_ / TPB, BATCH_), TPB>>>(Ac, Xc, prevh, Hc);
    k_scan3<<<gS, TPB>>>(aarr, xn, ybr, Hc, hhi);

    // out = (h*y) @ w_out^T + b_out   (1-term)
    k_gemm<0,1><<<gBig, TPB, SM1>>>(hhi, hhi, HID_, 0, woh, woh, HID_, 0,
                                    b_out, out, HID_, 0, HID_);
}

// round 8
// speedup vs baseline: 2.5076x; 1.1153x over previous
#include <cuda_runtime.h>
#include <cuda_fp16.h>
#include <math.h>
#include <stdint.h>

#define BATCH_ 2
#define SEQ_ 4096
#define HID_ 2560
#define HEADS_ 10
#define BW_ 256
#define MTOK_ (BATCH_*SEQ_)
#define CH_ 128           // scan chunks
#define CL_ 32            // steps per chunk

static constexpr long MD = (long)MTOK_ * HID_;   // 20,971,520
static constexpr long DD = (long)HID_ * HID_;    //  6,553,600
static constexpr long GD = (long)BW_  * HID_;    //    655,360
static constexpr long CD = (long)BATCH_ * CH_ * HID_;  // 655,360

// ---- scratch arena ----
static constexpr long O_XHI = 0;
static constexpr long O_CHI = O_XHI + MD*2;
static constexpr long O_CLO = O_CHI + MD*2;
static constexpr long O_HHI = O_CLO + MD*2;
static constexpr long O_WYH = O_HHI + MD*2;
static constexpr long O_WXH = O_WYH + DD*2;
static constexpr long O_WOH = O_WXH + DD*2;
static constexpr long O_IGH = O_WOH + DD*2;
static constexpr long O_IGL = O_IGH + GD*2;
static constexpr long O_AGH = O_IGL + GD*2;
static constexpr long O_AGL = O_AGH + GD*2;
static constexpr long O_SP8 = O_AGL + GD*2;
static constexpr long O_YBR = O_SP8 + HID_*4;
static constexpr long O_XBR = O_YBR + MD*4;
static constexpr long O_GX  = O_XBR + MD*4;
static constexpr long O_GA  = O_GX  + MD*4;
static constexpr long O_A   = O_GA  + MD*4;
static constexpr long O_XN  = O_A   + MD*4;
static constexpr long O_AC  = O_XN  + MD*4;
static constexpr long O_XC  = O_AC  + CD*4;
static constexpr long O_HC  = O_XC  + CD*4;
static constexpr long O_TOTAL = O_HC + CD*4;

__device__ __align__(256) unsigned char g_scratch[O_TOTAL];

// =====================================================================
// elementwise kernels (float4)
// =====================================================================
__device__ __forceinline__ void split1(float v, half& h, half& l) {
    h = __float2half(v);
    l = __float2half(v - __half2float(h));
}

// hi+lo split (gate weights)
__global__ void k_split4(const float* __restrict__ src, half* __restrict__ hi,
                         half* __restrict__ lo, long n4) {
    long i = (long)blockIdx.x * blockDim.x + threadIdx.x;
    if (i >= n4) return;
    float4 v = ((const float4*)src)[i];
    half h0, h1, h2, h3, l0, l1, l2, l3;
    split1(v.x, h0, l0); split1(v.y, h1, l1);
    split1(v.z, h2, l2); split1(v.w, h3, l3);
    ((half2*)hi)[2 * i]     = __halves2half2(h0, h1);
    ((half2*)hi)[2 * i + 1] = __halves2half2(h2, h3);
    ((half2*)lo)[2 * i]     = __halves2half2(l0, l1);
    ((half2*)lo)[2 * i + 1] = __halves2half2(l2, l3);
}

// hi-only
__global__ void k_splith(const float* __restrict__ src, half* __restrict__ hi, long n4) {
    long i = (long)blockIdx.x * blockDim.x + threadIdx.x;
    if (i >= n4) return;
    float4 v = ((const float4*)src)[i];
    ((half2*)hi)[2 * i]     = __halves2half2(__float2half(v.x), __float2half(v.y));
    ((half2*)hi)[2 * i + 1] = __halves2half2(__float2half(v.z), __float2half(v.w));
}

// per-channel -8*softplus(a_param)  (2560 elements, accurate path)
__global__ void k_sp(const float* __restrict__ ap, float* __restrict__ sp8) {
    int d = blockIdx.x * blockDim.x + threadIdx.x;
    if (d >= HID_) return;
    float v = ap[d];
    float sp = (v > 20.f) ? v : log1pf(expf(v));
    sp8[d] = -8.f * sp;
}

// depthwise causal conv -> fp16 hi/lo pair ONLY (no float copy; consumers
// reconstruct cf = hi+lo to ~2^-24)
__global__ void k_conv4(const float* __restrict__ xb, const float* __restrict__ cw,
                        const float* __restrict__ cb,
                        half* __restrict__ chi, half* __restrict__ clo) {
    long e = ((long)blockIdx.x * blockDim.x + threadIdx.x) * 4;
    if (e >= MD) return;
    int d = (int)(e % HID_);
    long bs = e / HID_;
    int s = (int)(bs % SEQ_);
    float4 acc = *(const float4*)(cb + d);
#pragma unroll
    for (int k = 0; k < 4; k++) {
        if (s + k - 3 >= 0) {
            float4 xv = *(const float4*)(xb + e + (long)(k - 3) * HID_);
            acc.x += xv.x * cw[(d + 0) * 4 + k];
            acc.y += xv.y * cw[(d + 1) * 4 + k];
            acc.z += xv.z * cw[(d + 2) * 4 + k];
            acc.w += xv.w * cw[(d + 3) * 4 + k];
        }
    }
    half h0, h1, h2, h3, l0, l1, l2, l3;
    split1(acc.x, h0, l0); split1(acc.y, h1, l1);
    split1(acc.z, h2, l2); split1(acc.w, h3, l3);
    *(half2*)(chi + e)     = __halves2half2(h0, h1);
    *(half2*)(chi + e + 2) = __halves2half2(h2, h3);
    *(half2*)(clo + e)     = __halves2half2(l0, l1);
    *(half2*)(clo + e + 2) = __halves2half2(l2, l3);
}

// =====================================================================
// fused coefficient-prep + chunk-local scan (pass 1)
// =====================================================================
__global__ void k_prescan(const int* __restrict__ pos32, const float* __restrict__ sp8,
                          const float* __restrict__ ga, const float* __restrict__ gx,
                          const half* __restrict__ chi, const half* __restrict__ clo,
                          float* __restrict__ A, float* __restrict__ XN,
                          float* __restrict__ Ac, float* __restrict__ Xc) {
    int d = blockIdx.x * blockDim.x + threadIdx.x;
    int c = blockIdx.y, b = blockIdx.z;
    long base = ((long)b * SEQ_ + (long)c * CL_) * HID_ + d;
    long bs0 = (long)b * SEQ_ + (long)c * CL_;
    bool is64 = (pos32[1] == 0);
    float sp = sp8[d];
    float h = 0.f, p = 1.f;
#pragma unroll 4
    for (int j = 0; j < CL_; j++) {
        long id = base + (long)j * HID_;
        long bs = bs0 + j;
        bool reset;
        if (is64) reset = (pos32[2 * bs] == 0) && (pos32[2 * bs + 1] == 0);
        else      reset = (pos32[bs] == 0);
        float cf = __half2float(chi[id]) + __half2float(clo[id]);
        float la = ga[id] * sp;          // -8 * gate_a * softplus(ap)
        float a = __expf(la);
        float mult = reset ? 1.f : sqrtf(fmaxf(1.f - a * a, 0.f));
        float x = cf * gx[id] * mult;
        a = reset ? 0.f : a;
        A[id] = a; XN[id] = x;
        h = fmaf(a, h, x);
        p *= a;
    }
    long o = ((long)b * CH_ + c) * HID_ + d;
    Ac[o] = p; Xc[o] = h;
}

__global__ void k_scan2(const float* __restrict__ Ac, const float* __restrict__ Xc,
                        const float* __restrict__ ph, float* __restrict__ Hc) {
    int d = blockIdx.x * blockDim.x + threadIdx.x;
    int b = blockIdx.y;
    float h = ph[(long)b * HID_ + d];
    long base = (long)b * CH_ * HID_ + d;
    for (int c = 0; c < CH_; c += 8) {
        float av[8], xv[8];
#pragma unroll
        for (int j = 0; j < 8; j++) {
            long id = base + (long)(c + j) * HID_;
            av[j] = Ac[id]; xv[j] = Xc[id];
        }
#pragma unroll
        for (int j = 0; j < 8; j++) {
            long id = base + (long)(c + j) * HID_;
            Hc[id] = h;
            h = fmaf(av[j], h, xv[j]);
        }
    }
}

__global__ void k_scan3(const float* __restrict__ A, const float* __restrict__ XN,
                        const float* __restrict__ Y, const float* __restrict__ Hc,
                        half* __restrict__ hhi) {
    int d = blockIdx.x * blockDim.x + threadIdx.x;
    int c = blockIdx.y, b = blockIdx.z;
    long base = ((long)b * SEQ_ + (long)c * CL_) * HID_ + d;
    float h = Hc[((long)b * CH_ + c) * HID_ + d];
#pragma unroll 4
    for (int j = 0; j < CL_; j++) {
        long id = base + (long)j * HID_;
        h = fmaf(A[id], h, XN[id]);
        hhi[id] = __float2half(h * Y[id]);   // out GEMM is 1-term; hi only
    }
}

// =====================================================================
// fp16-split GEMM:  C[m,n] = sum_k A[m,k]*W[n,k] + bias[n]
// TERMS=1: AhiWhi                  (y-branch, x-branch, out GEMM)
// TERMS=3: + AloWhi + AhiWlo       (gate GEMMs — protects the exp channel)
// tiles: 128x128x32, 8 warps (4x2), warp tile 32x64, mma.m16n8k16 f16
// 3-stage cp.async pipeline, one __syncthreads per K-iter.
// =====================================================================
#define GBM 128
#define GBN 128
#define GBK 32
#define KP  40
#define NST 3
#define PLN (GBM * KP)          // 5120 halves per plane

// fast, saturation-safe tanh/sigmoid via __expf (rel err ~1e-6)
__device__ __forceinline__ float fast_tanh(float u) {
    float e = __expf(2.f * u);
    return 1.f - 2.f / (e + 1.f);
}
__device__ __forceinline__ float gelu_tanh(float x) {
    float x3 = x * x * x;
    float t = fast_tanh(0.7978845608028654f * (x + 0.044715f * x3));
    return 0.5f * x * (1.f + t);
}
__device__ __forceinline__ float fast_sigmoid(float v) {
    return 1.f / (1.f + __expf(-v));
}

#define LDM4(r0, r1, r2, r3, addr)                                          \
    asm volatile("ldmatrix.sync.aligned.m8n8.x4.shared.b16 {%0,%1,%2,%3}, [%4];\n" \
                 : "=r"(r0), "=r"(r1), "=r"(r2), "=r"(r3) : "r"(addr))

#define MMA(d, a, b)                                                        \
    asm volatile("mma.sync.aligned.m16n8k16.row.col.f32.f16.f16.f32 "       \
                 "{%0,%1,%2,%3},{%4,%5,%6,%7},{%8,%9},{%0,%1,%2,%3};\n"     \
                 : "+f"(d[0]), "+f"(d[1]), "+f"(d[2]), "+f"(d[3])           \
                 : "r"(a[0]), "r"(a[1]), "r"(a[2]), "r"(a[3]),              \
                   "r"(b[0]), "r"(b[1]))

#define CP16(saddr, gptr)                                                   \
    asm volatile("cp.async.cg.shared.global [%0], [%1], 16;\n" ::           \
                 "r"(saddr), "l"(gptr))

template <int EPI, int TERMS>  // EPI: 0=bias, 1=+gelu, 2=+sigmoid
__global__ __launch_bounds__(256, 2) void k_gemm(
    const half* __restrict__ Ahi, const half* __restrict__ Alo, int lda, long az,
    const half* __restrict__ Bhi, const half* __restrict__ Blo, int ldb, long bz,
    const float* __restrict__ bias, float* __restrict__ C, int ldc, long cz, int K) {
    constexpr int PL = TERMS + 1;                 // planes per stage
    constexpr int PBH = (TERMS >= 2) ? 2 : 1;     // B-hi plane index
    extern __shared__ unsigned char smraw[];

    const int tid = threadIdx.x;
    const int lane = tid & 31;
    const int warp = tid >> 5;
    const int wm = warp & 3, wn = warp >> 2;
    const int g = lane >> 2, tg = lane & 3;
    const long mbase = (long)blockIdx.y * GBM;
    const long nbase = (long)blockIdx.x * GBN;
    const long z = blockIdx.z;

    const half* pAh = Ahi + z * az + mbase * lda;
    const half* pAl = Alo + z * az + mbase * lda;
    const half* pBh = Bhi + z * bz + nbase * ldb;
    const half* pBl = Blo + z * bz + nbase * ldb;

    unsigned su = (unsigned)__cvta_generic_to_shared(smraw);

    float acc[2][8][4];
#pragma unroll
    for (int a = 0; a < 2; a++)
#pragma unroll
        for (int b = 0; b < 8; b++)
#pragma unroll
            for (int c = 0; c < 4; c++) acc[a][b][c] = 0.f;

    const int T = K / GBK;
    const int lrow = tid >> 2;
    const int lcol = (tid & 3) * 8;

    auto issue = [&](int t) {
        int st = t % NST;
        long ko = (long)t * GBK;
        unsigned sb = su + (unsigned)(st * PL * PLN * 2);
#pragma unroll
        for (int i = 0; i < 2; i++) {
            int r = lrow + i * 64;
            unsigned off = (unsigned)((r * KP + lcol) * 2);
            CP16(sb + off, pAh + (long)r * lda + ko + lcol);
            if (TERMS >= 2)
                CP16(sb + off + PLN * 2, pAl + (long)r * lda + ko + lcol);
            CP16(sb + off + PBH * PLN * 2, pBh + (long)r * ldb + ko + lcol);
            if (TERMS == 3)
                CP16(sb + off + 3 * PLN * 2, pBl + (long)r * ldb + ko + lcol);
        }
        asm volatile("cp.async.commit_group;\n" ::: "memory");
    };

    auto compute = [&](int st) {
        unsigned sb = su + (unsigned)(st * PL * PLN * 2);
#pragma unroll
        for (int kk = 0; kk < 2; kk++) {
            unsigned ah[2][4], al[2][4], bh[8][2], bl[8][2];
#pragma unroll
            for (int mt = 0; mt < 2; mt++) {
                int r = wm * 32 + mt * 16 + (lane & 7) + ((lane >> 3) & 1) * 8;
                int c = kk * 16 + (lane >> 4) * 8;
                unsigned a0 = sb + (unsigned)((r * KP + c) * 2);
                LDM4(ah[mt][0], ah[mt][1], ah[mt][2], ah[mt][3], a0);
                if (TERMS >= 2)
                    LDM4(al[mt][0], al[mt][1], al[mt][2], al[mt][3], a0 + PLN * 2);
            }
#pragma unroll
            for (int np = 0; np < 4; np++) {
                int i = lane >> 3;
                int r = wn * 64 + np * 16 + ((i >> 1) & 1) * 8 + (lane & 7);
                int c = kk * 16 + (i & 1) * 8;
                unsigned b0 = sb + (unsigned)((r * KP + c) * 2) + PBH * PLN * 2;
                LDM4(bh[2 * np][0], bh[2 * np][1], bh[2 * np + 1][0], bh[2 * np + 1][1], b0);
                if (TERMS == 3)
                    LDM4(bl[2 * np][0], bl[2 * np][1], bl[2 * np + 1][0], bl[2 * np + 1][1],
                         b0 + PLN * 2);
            }
#pragma unroll
            for (int mt = 0; mt < 2; mt++)
#pragma unroll
                for (int nt = 0; nt < 8; nt++) {
                    MMA(acc[mt][nt], ah[mt], bh[nt]);
                    if (TERMS >= 2) MMA(acc[mt][nt], al[mt], bh[nt]);
                    if (TERMS == 3) MMA(acc[mt][nt], ah[mt], bl[nt]);
                }
        }
    };

    // prologue: fill 2 of 3 stages
    issue(0);
    issue(1);
    for (int t = 0; t < T; t++) {
        asm volatile("cp.async.wait_group 1;\n" ::: "memory");  // stage t ready
        __syncthreads();
        if (t + 2 < T) issue(t + 2);
        compute(t % NST);
    }

    // epilogue
#pragma unroll
    for (int mt = 0; mt < 2; mt++) {
        long r0 = mbase + wm * 32 + mt * 16 + g;
#pragma unroll
        for (int nt = 0; nt < 8; nt++) {
            long col = (long)(wn * 64 + nt * 8 + tg * 2);
            long gcol = nbase + col;
            float b0 = bias[gcol], b1 = bias[gcol + 1];
            float v0 = acc[mt][nt][0] + b0;
            float v1 = acc[mt][nt][1] + b1;
            float v2 = acc[mt][nt][2] + b0;
            float v3 = acc[mt][nt][3] + b1;
            if (EPI == 1) {
                v0 = gelu_tanh(v0); v1 = gelu_tanh(v1);
                v2 = gelu_tanh(v2); v3 = gelu_tanh(v3);
            } else if (EPI == 2) {
                v0 = fast_sigmoid(v0); v1 = fast_sigmoid(v1);
                v2 = fast_sigmoid(v2); v3 = fast_sigmoid(v3);
            }
            float* cp = C + z * cz;
            *(float2*)(cp + r0 * ldc + gcol)       = make_float2(v0, v1);
            *(float2*)(cp + (r0 + 8) * ldc + gcol) = make_float2(v2, v3);
        }
    }
}

// =====================================================================
// launch
// =====================================================================
extern "C" void kernel_launch(void* const* d_in, const int* in_sizes, int n_in,
                              void* d_out, int out_size) {
    const float* X       = (const float*)d_in[0];
    const int*   pos32   = (const int*)d_in[1];
    const float* prevh   = (const float*)d_in[2];
    const float* w_y     = (const float*)d_in[3];
    const float* b_y     = (const float*)d_in[4];
    const float* w_x     = (const float*)d_in[5];
    const float* b_x     = (const float*)d_in[6];
    const float* w_out   = (const float*)d_in[7];
    const float* b_out   = (const float*)d_in[8];
    const float* conv_w  = (const float*)d_in[9];
    const float* conv_b  = (const float*)d_in[10];
    const float* a_param = (const float*)d_in[11];
    const float* ig_w    = (const float*)d_in[12];
    const float* ig_b    = (const float*)d_in[13];
    const float* ag_w    = (const float*)d_in[14];
    const float* ag_b    = (const float*)d_in[15];
    float* out = (float*)d_out;

    unsigned char* base = nullptr;
    cudaGetSymbolAddress((void**)&base, g_scratch);

    half*  xhi  = (half*)(base + O_XHI);
    half*  chi  = (half*)(base + O_CHI);  half* clo  = (half*)(base + O_CLO);
    half*  hhi  = (half*)(base + O_HHI);
    half*  wyh  = (half*)(base + O_WYH);
    half*  wxh  = (half*)(base + O_WXH);
    half*  woh  = (half*)(base + O_WOH);
    half*  igh  = (half*)(base + O_IGH);  half* igl  = (half*)(base + O_IGL);
    half*  agh  = (half*)(base + O_AGH);  half* agl  = (half*)(base + O_AGL);
    float* sp8  = (float*)(base + O_SP8);
    float* ybr  = (float*)(base + O_YBR);
    float* xbr  = (float*)(base + O_XBR);
    float* gx   = (float*)(base + O_GX);
    float* ga   = (float*)(base + O_GA);
    float* aarr = (float*)(base + O_A);
    float* xn   = (float*)(base + O_XN);
    float* Ac   = (float*)(base + O_AC);
    float* Xc   = (float*)(base + O_XC);
    float* Hc   = (float*)(base + O_HC);

    const int SM1 = NST * 2 * PLN * 2;   // 61440 B  (1-term: A hi + B hi)
    const int SM3 = NST * 4 * PLN * 2;   // 122880 B (3-term)
    cudaFuncSetAttribute((void*)k_gemm<1,1>, cudaFuncAttributeMaxDynamicSharedMemorySize, SM1);
    cudaFuncSetAttribute((void*)k_gemm<0,1>, cudaFuncAttributeMaxDynamicSharedMemorySize, SM1);
    cudaFuncSetAttribute((void*)k_gemm<2,3>, cudaFuncAttributeMaxDynamicSharedMemorySize, SM3);

    const int TPB = 256;
    dim3 gBig(HID_ / GBN, MTOK_ / GBM, 1);

    // splits + per-channel softplus table
    k_splith<<<(int)((MD / 4 + TPB - 1) / TPB), TPB>>>(X, xhi, MD / 4);
    k_splith<<<(int)((DD / 4 + TPB - 1) / TPB), TPB>>>(w_y, wyh, DD / 4);
    k_splith<<<(int)((DD / 4 + TPB - 1) / TPB), TPB>>>(w_x, wxh, DD / 4);
    k_splith<<<(int)((DD / 4 + TPB - 1) / TPB), TPB>>>(w_out, woh, DD / 4);
    k_split4<<<(int)((GD / 4 + TPB - 1) / TPB), TPB>>>(ig_w, igh, igl, GD / 4);
    k_sp<<<(HID_ + TPB - 1) / TPB, TPB>>>(a_param, sp8);

    // y-branch: gelu(X @ w_y^T + b_y)   (1-term)
    k_gemm<1,1><<<gBig, TPB, SM1>>>(xhi, xhi, HID_, 0, wyh, wyh, HID_, 0,
                                    b_y, ybr, HID_, 0, HID_);

    k_split4<<<(int)((GD / 4 + TPB - 1) / TPB), TPB>>>(ag_w, agh, agl, GD / 4);

    // x-branch: X @ w_x^T + b_x   (1-term)
    k_gemm<0,1><<<gBig, TPB, SM1>>>(xhi, xhi, HID_, 0, wxh, wxh, HID_, 0,
                                    b_x, xbr, HID_, 0, HID_);

    // depthwise causal conv -> fp16 hi/lo only
    k_conv4<<<(int)((MD / 4 + TPB - 1) / TPB), TPB>>>(xbr, conv_w, conv_b, chi, clo);

    // block-diagonal gates (z = head) — 3-term, protects the exp channel
    dim3 gGate(BW_ / GBN, MTOK_ / GBM, HEADS_);
    k_gemm<2,3><<<gGate, TPB, SM3>>>(chi, clo, HID_, (long)BW_,
                                     igh, igl, BW_, (long)BW_ * BW_,
                                     ig_b, gx, HID_, (long)BW_, BW_);
    k_gemm<2,3><<<gGate, TPB, SM3>>>(chi, clo, HID_, (long)BW_,
                                     agh, agl, BW_, (long)BW_ * BW_,
                                     ag_b, ga, HID_, (long)BW_, BW_);

    // fused prep + chunk-local scan (pass 1)
    dim3 gS(HID_ / TPB, CH_, BATCH_);
    k_prescan<<<gS, TPB>>>(pos32, sp8, ga, gx, chi, clo, aarr, xn, Ac, Xc);
    k_scan2<<<dim3(HID_ / TPB, BATCH_), TPB>>>(Ac, Xc, prevh, Hc);
    k_scan3<<<gS, TPB>>>(aarr, xn, ybr, Hc, hhi);

    // out = (h*y) @ w_out^T + b_out   (1-term)
    k_gemm<0,1><<<gBig, TPB, SM1>>>(hhi, hhi, HID_, 0, woh, woh, HID_, 0,
                                    b_out, out, HID_, 0, HID_);
}